// round 11
// baseline (speedup 1.0000x reference)
#include <cuda_runtime.h>
#include <cuda_bf16.h>
#include <math.h>
#include <cstdint>

// ContrastiveLoss N=8192 D=128 temp=0.05 — plain-bf16 HMMA, symmetric tiles,
// fused high-MLP y load, 3 CTAs/SM, fused final reduction.
// loss = -mean_i [ (1/ppn_i) * sum_{j: y_ij=1} log( e_ij / (e_ij + nl_i) ) ]
// log(e/(e+nl)) = -log1p(nl*exp(-t)), t = cos/T.

#define NN 8192
#define DD 128
#define INV_T 20.0f
#define NSLOT 192            // nl partial slots: row-role 0..127, col-role 128..191
#define BLK_POS 32           // positive slots per (row, 128-col block)
#define POS_STRIDE 2048      // 64 blocks * 32

__device__ __nv_bfloat16 g_xhi[NN * DD];
__device__ float g_nl_part[(size_t)NN * NSLOT];
__device__ int   g_bcnt[(size_t)NN * 64];
__device__ float g_pos[(size_t)NN * POS_STRIDE];

// ---------------------------------------------------------------------------
__device__ __forceinline__ uint32_t smem_u32(const void* p) {
    uint32_t a;
    asm("{ .reg .u64 t; cvta.to.shared.u64 t, %1; cvt.u32.u64 %0, t; }" : "=r"(a) : "l"(p));
    return a;
}
__device__ __forceinline__ void ldmx4(uint32_t* r, uint32_t addr) {
    asm volatile("ldmatrix.sync.aligned.m8n8.x4.shared.b16 {%0,%1,%2,%3}, [%4];"
        : "=r"(r[0]), "=r"(r[1]), "=r"(r[2]), "=r"(r[3]) : "r"(addr));
}
__device__ __forceinline__ void mma_bf16(float* d, const uint32_t* a,
                                         uint32_t b0, uint32_t b1) {
    asm volatile("mma.sync.aligned.m16n8k16.row.col.f32.bf16.bf16.f32 "
        "{%0,%1,%2,%3}, {%4,%5,%6,%7}, {%8,%9}, {%0,%1,%2,%3};"
        : "+f"(d[0]), "+f"(d[1]), "+f"(d[2]), "+f"(d[3])
        : "r"(a[0]), "r"(a[1]), "r"(a[2]), "r"(a[3]), "r"(b0), "r"(b1));
}
__device__ __forceinline__ unsigned nib4(float4 v) {
    return (unsigned)(v.x != 0.0f) | ((unsigned)(v.y != 0.0f) << 1)
         | ((unsigned)(v.z != 0.0f) << 2) | ((unsigned)(v.w != 0.0f) << 3);
}

// ---------------------------------------------------------------------------
__global__ void k_normalize(const float* __restrict__ x, float* __restrict__ out) {
    if (blockIdx.x == 0 && threadIdx.x == 0) out[0] = 0.0f;
    int row  = blockIdx.x * 8 + (threadIdx.x >> 5);
    int lane = threadIdx.x & 31;
    float4 v = ((const float4*)(x + (size_t)row * DD))[lane];
    float ss = v.x * v.x + v.y * v.y + v.z * v.z + v.w * v.w;
    #pragma unroll
    for (int o = 16; o; o >>= 1) ss += __shfl_xor_sync(0xFFFFFFFFu, ss, o);
    float inv = rsqrtf(ss);
    float f[4] = {v.x * inv, v.y * inv, v.z * inv, v.w * inv};
    ushort4 hi4;
    unsigned short* hp = &hi4.x;
    #pragma unroll
    for (int i = 0; i < 4; i++) {
        __nv_bfloat16 h = __float2bfloat16(f[i]);
        hp[i] = *(unsigned short*)&h;
    }
    ((ushort4*)(g_xhi + (size_t)row * DD))[lane] = hi4;
}

// ---------------------------------------------------------------------------
__global__ void k_pad() {}   // keeps k_tile at launch index 3 (ncu capture slot)

// ---------------------------------------------------------------------------
// HMMA tile GEMM + fused high-MLP y load + dual-role epilogue. Triangular grid.
// SMEM: A@0 (32K), B@32768 (32K), yb@65536 (2K), pf(short)@67584 (1K),
//       yb2@68608 (2K), pf2(short)@70656 (1K). Total 71680. 3 CTAs/SM.
#define SM_A   0
#define SM_B   32768
#define SM_YB  65536
#define SM_PF  67584
#define SM_YB2 68608
#define SM_PF2 70656
#define SM_TOT 71680
#define NBLK   2080          // 64*65/2

__global__ void __launch_bounds__(256, 3) k_tile(const float* __restrict__ y) {
    int bi = 0, rem = blockIdx.x;
    while (rem >= 64 - bi) { rem -= 64 - bi; bi++; }
    const int bj = bi + rem;
    const bool offdiag = (bi != bj);

    extern __shared__ char smem[];
    uint32_t sbase = smem_u32(smem);
    const int tid  = threadIdx.x;
    const int wid  = tid >> 5;
    const int lane = tid & 31;
    const int warp_m = wid >> 1;
    const int warp_n = wid & 1;
    const int row0 = bi * 128;
    const int col0 = bj * 128;

    unsigned* yb  = (unsigned*)(smem + SM_YB);
    short*    pf  = (short*)(smem + SM_PF);
    unsigned* yb2 = (unsigned*)(smem + SM_YB2);
    short*    pf2 = (short*)(smem + SM_PF2);

    // ---- load A/B tiles (L2-resident bf16)
    {
        const uint4* ah = (const uint4*)(g_xhi + (size_t)row0 * DD);
        const uint4* bh = (const uint4*)(g_xhi + (size_t)col0 * DD);
        #pragma unroll
        for (int i = 0; i < 8; i++) {
            int idx = tid + i * 256;
            int r   = idx >> 4;
            int c   = idx & 15;
            uint32_t so = (uint32_t)r * 256 + (uint32_t)((c ^ (r & 7)) * 16);
            *(uint4*)(smem + SM_A + so) = ah[idx];
            *(uint4*)(smem + SM_B + so) = bh[idx];
        }
    }

    // ---- y load, high MLP: 8 threads per row, 4 consecutive float4 each
    {
        const int q8 = tid & 7;
        #pragma unroll
        for (int p = 0; p < 4; p++) {
            int r = p * 32 + (tid >> 3);
            const float4* yr = (const float4*)(y + (size_t)(row0 + r) * NN + col0) + q8 * 4;
            unsigned m = 0;
            #pragma unroll
            for (int k = 0; k < 4; k++) m |= nib4(yr[k]) << (k * 4);
            unsigned o = __shfl_xor_sync(0xFFFFFFFFu, m, 1);
            if (!(tid & 1)) yb[r * 4 + (q8 >> 1)] = m | (o << 16);
            if (offdiag) {
                const float4* yc = (const float4*)(y + (size_t)(col0 + r) * NN + row0) + q8 * 4;
                unsigned m2 = 0;
                #pragma unroll
                for (int k = 0; k < 4; k++) m2 |= nib4(yc[k]) << (k * 4);
                unsigned o2 = __shfl_xor_sync(0xFFFFFFFFu, m2, 1);
                if (!(tid & 1)) yb2[r * 4 + (q8 >> 1)] = m2 | (o2 << 16);
            }
        }
    }
    __syncthreads();

    // ---- within-segment prefixes + per-(row,block) counts
    if (tid < 128) {
        int r = tid;
        unsigned w0 = yb[r * 4], w1 = yb[r * 4 + 1], w2 = yb[r * 4 + 2], w3 = yb[r * 4 + 3];
        int c0 = __popc(w0), c1 = __popc(w1), c2 = __popc(w2), c3 = __popc(w3);
        pf[r * 4] = 0; pf[r * 4 + 1] = (short)c0;
        pf[r * 4 + 2] = (short)(c0 + c1); pf[r * 4 + 3] = (short)(c0 + c1 + c2);
        g_bcnt[(size_t)(row0 + r) * 64 + bj] = c0 + c1 + c2 + c3;
    } else if (offdiag) {
        int c = tid - 128;
        unsigned w0 = yb2[c * 4], w1 = yb2[c * 4 + 1], w2 = yb2[c * 4 + 2], w3 = yb2[c * 4 + 3];
        int c0 = __popc(w0), c1 = __popc(w1), c2 = __popc(w2), c3 = __popc(w3);
        pf2[c * 4] = 0; pf2[c * 4 + 1] = (short)c0;
        pf2[c * 4 + 2] = (short)(c0 + c1); pf2[c * 4 + 3] = (short)(c0 + c1 + c2);
        g_bcnt[(size_t)(col0 + c) * 64 + bi] = c0 + c1 + c2 + c3;
    }
    __syncthreads();

    // ---- mainloop
    float acc[2][8][4];
    #pragma unroll
    for (int i = 0; i < 2; i++)
        #pragma unroll
        for (int j = 0; j < 8; j++)
            #pragma unroll
            for (int q = 0; q < 4; q++) acc[i][j][q] = 0.0f;

    const uint32_t lane_row = lane & 15;
    const uint32_t kb  = lane >> 4;
    const uint32_t key = lane & 7;
    const uint32_t a_base = sbase + SM_A + (warp_m * 32 + lane_row) * 256;
    const uint32_t b_base = sbase + SM_B + (warp_n * 64 + lane_row) * 256;

    #pragma unroll
    for (int k16 = 0; k16 < 8; k16++) {
        uint32_t ca = (((uint32_t)k16 * 2 + kb) ^ key) * 16;
        uint32_t a0[4], a1[4];
        ldmx4(a0, a_base + ca);
        ldmx4(a1, a_base + 4096 + ca);
        #pragma unroll
        for (int n16 = 0; n16 < 4; n16++) {
            uint32_t bf[4];
            ldmx4(bf, b_base + n16 * 4096 + ca);
            mma_bf16(acc[0][n16 * 2 + 0], a0, bf[0], bf[2]);
            mma_bf16(acc[0][n16 * 2 + 1], a0, bf[1], bf[3]);
            mma_bf16(acc[1][n16 * 2 + 0], a1, bf[0], bf[2]);
            mma_bf16(acc[1][n16 * 2 + 1], a1, bf[1], bf[3]);
        }
    }
    __syncthreads();   // A/B smem dead; colred scratch takes over

    // ---- dual-role epilogue
    float* cr = (float*)(smem + SM_A);   // [32][132]
    const int qm = lane >> 2;
    const int qn = (lane & 3) * 2;
    const int g  = warp_m * 8 + qm;
    float negLo[2] = {0.f, 0.f};
    float negHi[2] = {0.f, 0.f};

    #pragma unroll
    for (int n8 = 0; n8 < 8; n8++) {
        const int half = n8 >> 2;
        const int w = warp_n * 2 + half;
        const int p = (n8 & 3) * 8 + qn;
        const unsigned m0 = 1u << p, m1 = m0 << 1;
        const int clA = warp_n * 64 + n8 * 8 + qn;
        unsigned w2c0 = 0, w2c1 = 0;
        int pf2c0 = 0, pf2c1 = 0;
        if (offdiag) {
            w2c0 = yb2[clA * 4 + warp_m];       pf2c0 = pf2[clA * 4 + warp_m];
            w2c1 = yb2[(clA + 1) * 4 + warp_m]; pf2c1 = pf2[(clA + 1) * 4 + warp_m];
        }
        float negc0 = 0.0f, negc1 = 0.0f;
        #pragma unroll
        for (int m_i = 0; m_i < 2; m_i++) {
            const int rlo = warp_m * 32 + m_i * 16 + qm;
            const int rhi = rlo + 8;
            const unsigned wordL = yb[rlo * 4 + w];
            const unsigned wordH = yb[rhi * 4 + w];
            const int prefL = pf[rlo * 4 + w];
            const int prefH = pf[rhi * 4 + w];
            const float* d = acc[m_i][n8];
            float t0 = d[0] * INV_T, t1 = d[1] * INV_T;
            float t2 = d[2] * INV_T, t3 = d[3] * INV_T;
            float e0 = __expf(t0), e1 = __expf(t1);
            float e2 = __expf(t2), e3 = __expf(t3);
            negLo[m_i] += (wordL & m0) ? 0.0f : e0;
            negLo[m_i] += (wordL & m1) ? 0.0f : e1;
            negHi[m_i] += (wordH & m0) ? 0.0f : e2;
            negHi[m_i] += (wordH & m1) ? 0.0f : e3;
            float* gposL = g_pos + (size_t)(row0 + rlo) * POS_STRIDE + bj * BLK_POS;
            float* gposH = g_pos + (size_t)(row0 + rhi) * POS_STRIDE + bj * BLK_POS;
            if (wordL & m0) gposL[prefL + __popc(wordL & (m0 - 1))] = t0;
            if (wordL & m1) gposL[prefL + __popc(wordL & (m1 - 1))] = t1;
            if (wordH & m0) gposH[prefH + __popc(wordH & (m0 - 1))] = t2;
            if (wordH & m1) gposH[prefH + __popc(wordH & (m1 - 1))] = t3;
            if (offdiag) {
                const unsigned bL = 1u << (rlo & 31);
                const unsigned bH = 1u << (rhi & 31);
                negc0 += (w2c0 & bL) ? 0.0f : e0;
                negc0 += (w2c0 & bH) ? 0.0f : e2;
                negc1 += (w2c1 & bL) ? 0.0f : e1;
                negc1 += (w2c1 & bH) ? 0.0f : e3;
                float* gpc0 = g_pos + (size_t)(col0 + clA) * POS_STRIDE + bi * BLK_POS;
                float* gpc1 = g_pos + (size_t)(col0 + clA + 1) * POS_STRIDE + bi * BLK_POS;
                if (w2c0 & bL) gpc0[pf2c0 + __popc(w2c0 & (bL - 1))] = t0;
                if (w2c0 & bH) gpc0[pf2c0 + __popc(w2c0 & (bH - 1))] = t2;
                if (w2c1 & bL) gpc1[pf2c1 + __popc(w2c1 & (bL - 1))] = t1;
                if (w2c1 & bH) gpc1[pf2c1 + __popc(w2c1 & (bH - 1))] = t3;
            }
        }
        if (offdiag) {
            cr[g * 132 + clA]     = negc0;
            cr[g * 132 + clA + 1] = negc1;
        }
    }

    // row-role nl partials
    int slotR = bj * 2 + warp_n;
    #pragma unroll
    for (int m_i = 0; m_i < 2; m_i++) {
        float vlo = negLo[m_i], vhi = negHi[m_i];
        vlo += __shfl_xor_sync(0xFFFFFFFFu, vlo, 1);
        vlo += __shfl_xor_sync(0xFFFFFFFFu, vlo, 2);
        vhi += __shfl_xor_sync(0xFFFFFFFFu, vhi, 1);
        vhi += __shfl_xor_sync(0xFFFFFFFFu, vhi, 2);
        if ((lane & 3) == 0) {
            int r = row0 + warp_m * 32 + m_i * 16 + qm;
            g_nl_part[(size_t)r * NSLOT + slotR]       = vlo;
            g_nl_part[(size_t)(r + 8) * NSLOT + slotR] = vhi;
        }
    }

    // col-role nl reduce
    __syncthreads();
    if (offdiag && tid < 128) {
        float s = 0.0f;
        #pragma unroll
        for (int gg = 0; gg < 32; gg++) s += cr[gg * 132 + tid];
        g_nl_part[(size_t)(col0 + tid) * NSLOT + 128 + bi] = s;
    }
}

// ---------------------------------------------------------------------------
// Per-row loss + fused final reduction. 8 rows per block (one warp each).
__global__ void k_rowloss(float* __restrict__ out) {
    __shared__ float bsum[8];
    int row  = blockIdx.x * 8 + (threadIdx.x >> 5);
    int lane = threadIdx.x & 31;
    int wrp  = threadIdx.x >> 5;
    int br = row >> 7;
    const float* p = g_nl_part + (size_t)row * NSLOT;
    int lenR = 128 - 2 * br;
    int lenT = lenR + br;
    float nl = 0.0f;
    for (int i = lane; i < lenT; i += 32) {
        int s = (i < lenR) ? (2 * br + i) : (128 + (i - lenR));
        nl += p[s];
    }
    #pragma unroll
    for (int o = 16; o; o >>= 1) nl += __shfl_xor_sync(0xFFFFFFFFu, nl, o);

    const int* bc = g_bcnt + (size_t)row * 64;
    const float* ps = g_pos + (size_t)row * POS_STRIDE;
    float acc = 0.0f;
    int cnt = 0;
    #pragma unroll
    for (int bb = 0; bb < 2; bb++) {
        int b = lane + bb * 32;
        int c = bc[b];
        cnt += c;
        const float* pp = ps + b * BLK_POS;
        for (int k = 0; k < c; k++)
            acc += log1pf(nl * __expf(-pp[k]));
    }
    #pragma unroll
    for (int o = 16; o; o >>= 1) {
        acc += __shfl_xor_sync(0xFFFFFFFFu, acc, o);
        cnt += __shfl_xor_sync(0xFFFFFFFFu, cnt, o);
    }
    if (lane == 0) bsum[wrp] = acc / (float)cnt;
    __syncthreads();
    if (threadIdx.x == 0) {
        float s = 0.0f;
        #pragma unroll
        for (int i = 0; i < 8; i++) s += bsum[i];
        atomicAdd(out, s * (1.0f / (float)NN));
    }
}

// ---------------------------------------------------------------------------
extern "C" void kernel_launch(void* const* d_in, const int* in_sizes, int n_in,
                              void* d_out, int out_size) {
    const float* x = (const float*)d_in[0];
    const float* y = (const float*)d_in[1];
    float* out = (float*)d_out;

    cudaFuncSetAttribute(k_tile, cudaFuncAttributeMaxDynamicSharedMemorySize, SM_TOT);

    k_normalize<<<NN / 8, 256>>>(x, out);                // idx 0 (zeroes out)
    k_pad<<<1, 32>>>();                                  // idx 1
    k_pad<<<1, 32>>>();                                  // idx 2
    k_tile<<<NBLK, 256, SM_TOT>>>(y);                    // idx 3 (ncu slot)
    k_rowloss<<<NN / 8, 256>>>(out);                     // idx 4
}

// round 12
// speedup vs baseline: 1.2008x; 1.2008x over previous
#include <cuda_runtime.h>
#include <cuda_bf16.h>
#include <math.h>
#include <cstdint>

// ContrastiveLoss N=8192 D=128 temp=0.05 — plain-bf16 HMMA, symmetric tiles,
// fused high-MLP y load (issued before A/B), 2 CTAs/SM, fused final reduce.
// loss = -mean_i [ (1/ppn_i) * sum_{j: y_ij=1} log( e_ij / (e_ij + nl_i) ) ]
// log(e/(e+nl)) = -log1p(nl*exp(-t)), t = cos/T.

#define NN 8192
#define DD 128
#define INV_T 20.0f
#define INV_T_LOG2E 28.853900817779268f   // 20 * log2(e)
#define NSLOT 192            // nl partial slots: row-role 0..127, col-role 128..191
#define BLK_POS 32           // positive slots per (row, 128-col block)
#define POS_STRIDE 2048      // 64 blocks * 32

__device__ __nv_bfloat16 g_xhi[NN * DD];
__device__ float g_nl_part[(size_t)NN * NSLOT];
__device__ int   g_bcnt[(size_t)NN * 64];
__device__ float g_pos[(size_t)NN * POS_STRIDE];

// ---------------------------------------------------------------------------
__device__ __forceinline__ uint32_t smem_u32(const void* p) {
    uint32_t a;
    asm("{ .reg .u64 t; cvta.to.shared.u64 t, %1; cvt.u32.u64 %0, t; }" : "=r"(a) : "l"(p));
    return a;
}
__device__ __forceinline__ void ldmx4(uint32_t* r, uint32_t addr) {
    asm volatile("ldmatrix.sync.aligned.m8n8.x4.shared.b16 {%0,%1,%2,%3}, [%4];"
        : "=r"(r[0]), "=r"(r[1]), "=r"(r[2]), "=r"(r[3]) : "r"(addr));
}
__device__ __forceinline__ void mma_bf16(float* d, const uint32_t* a,
                                         uint32_t b0, uint32_t b1) {
    asm volatile("mma.sync.aligned.m16n8k16.row.col.f32.bf16.bf16.f32 "
        "{%0,%1,%2,%3}, {%4,%5,%6,%7}, {%8,%9}, {%0,%1,%2,%3};"
        : "+f"(d[0]), "+f"(d[1]), "+f"(d[2]), "+f"(d[3])
        : "r"(a[0]), "r"(a[1]), "r"(a[2]), "r"(a[3]), "r"(b0), "r"(b1));
}
__device__ __forceinline__ unsigned nib4(float4 v) {
    return (unsigned)(v.x != 0.0f) | ((unsigned)(v.y != 0.0f) << 1)
         | ((unsigned)(v.z != 0.0f) << 2) | ((unsigned)(v.w != 0.0f) << 3);
}

// ---------------------------------------------------------------------------
__global__ void k_normalize(const float* __restrict__ x, float* __restrict__ out) {
    if (blockIdx.x == 0 && threadIdx.x == 0) out[0] = 0.0f;
    int row  = blockIdx.x * 8 + (threadIdx.x >> 5);
    int lane = threadIdx.x & 31;
    float4 v = ((const float4*)(x + (size_t)row * DD))[lane];
    float ss = v.x * v.x + v.y * v.y + v.z * v.z + v.w * v.w;
    #pragma unroll
    for (int o = 16; o; o >>= 1) ss += __shfl_xor_sync(0xFFFFFFFFu, ss, o);
    float inv = rsqrtf(ss);
    float f[4] = {v.x * inv, v.y * inv, v.z * inv, v.w * inv};
    ushort4 hi4;
    unsigned short* hp = &hi4.x;
    #pragma unroll
    for (int i = 0; i < 4; i++) {
        __nv_bfloat16 h = __float2bfloat16(f[i]);
        hp[i] = *(unsigned short*)&h;
    }
    ((ushort4*)(g_xhi + (size_t)row * DD))[lane] = hi4;
}

// ---------------------------------------------------------------------------
__global__ void k_pad() {}   // keeps k_tile at launch index 3 (ncu capture slot)

// ---------------------------------------------------------------------------
// HMMA tile GEMM + fused y load + dual-role epilogue. Triangular grid.
#define SM_A   0
#define SM_B   32768
#define SM_YB  65536
#define SM_PF  67584
#define SM_YB2 69632
#define SM_PF2 71680
#define SM_TOT 73728
#define NBLK   2080          // 64*65/2

__global__ void __launch_bounds__(256, 2) k_tile(const float* __restrict__ y) {
    int bi = 0, rem = blockIdx.x;
    while (rem >= 64 - bi) { rem -= 64 - bi; bi++; }
    const int bj = bi + rem;
    const bool offdiag = (bi != bj);

    extern __shared__ char smem[];
    uint32_t sbase = smem_u32(smem);
    const int tid  = threadIdx.x;
    const int wid  = tid >> 5;
    const int lane = tid & 31;
    const int warp_m = wid >> 1;
    const int warp_n = wid & 1;
    const int row0 = bi * 128;
    const int col0 = bj * 128;

    unsigned* yb  = (unsigned*)(smem + SM_YB);
    int*      pf  = (int*)(smem + SM_PF);
    unsigned* yb2 = (unsigned*)(smem + SM_YB2);
    int*      pf2 = (int*)(smem + SM_PF2);

    // ---- y load FIRST (DRAM latency starts ticking), high MLP:
    // 8 threads per row, 4 consecutive float4 each; pairs merge via shfl.
    {
        const int q8 = tid & 7;
        #pragma unroll
        for (int p = 0; p < 4; p++) {
            int r = p * 32 + (tid >> 3);
            const float4* yr = (const float4*)(y + (size_t)(row0 + r) * NN + col0) + q8 * 4;
            unsigned m = 0;
            #pragma unroll
            for (int k = 0; k < 4; k++) m |= nib4(yr[k]) << (k * 4);
            unsigned o = __shfl_xor_sync(0xFFFFFFFFu, m, 1);
            if (!(tid & 1)) yb[r * 4 + (q8 >> 1)] = m | (o << 16);
            if (offdiag) {
                const float4* yc = (const float4*)(y + (size_t)(col0 + r) * NN + row0) + q8 * 4;
                unsigned m2 = 0;
                #pragma unroll
                for (int k = 0; k < 4; k++) m2 |= nib4(yc[k]) << (k * 4);
                unsigned o2 = __shfl_xor_sync(0xFFFFFFFFu, m2, 1);
                if (!(tid & 1)) yb2[r * 4 + (q8 >> 1)] = m2 | (o2 << 16);
            }
        }
    }

    // ---- A/B tile loads (L2-resident bf16) — fills y-latency shadow
    {
        const uint4* ah = (const uint4*)(g_xhi + (size_t)row0 * DD);
        const uint4* bh = (const uint4*)(g_xhi + (size_t)col0 * DD);
        #pragma unroll
        for (int i = 0; i < 8; i++) {
            int idx = tid + i * 256;
            int r   = idx >> 4;
            int c   = idx & 15;
            uint32_t so = (uint32_t)r * 256 + (uint32_t)((c ^ (r & 7)) * 16);
            *(uint4*)(smem + SM_A + so) = ah[idx];
            *(uint4*)(smem + SM_B + so) = bh[idx];
        }
    }
    __syncthreads();

    // ---- within-segment prefixes + per-(row,block) counts
    if (tid < 128) {
        int r = tid;
        unsigned w0 = yb[r * 4], w1 = yb[r * 4 + 1], w2 = yb[r * 4 + 2], w3 = yb[r * 4 + 3];
        int c0 = __popc(w0), c1 = __popc(w1), c2 = __popc(w2), c3 = __popc(w3);
        pf[r * 4] = 0; pf[r * 4 + 1] = c0; pf[r * 4 + 2] = c0 + c1; pf[r * 4 + 3] = c0 + c1 + c2;
        g_bcnt[(size_t)(row0 + r) * 64 + bj] = c0 + c1 + c2 + c3;
    } else if (offdiag) {
        int c = tid - 128;
        unsigned w0 = yb2[c * 4], w1 = yb2[c * 4 + 1], w2 = yb2[c * 4 + 2], w3 = yb2[c * 4 + 3];
        int c0 = __popc(w0), c1 = __popc(w1), c2 = __popc(w2), c3 = __popc(w3);
        pf2[c * 4] = 0; pf2[c * 4 + 1] = c0; pf2[c * 4 + 2] = c0 + c1; pf2[c * 4 + 3] = c0 + c1 + c2;
        g_bcnt[(size_t)(col0 + c) * 64 + bi] = c0 + c1 + c2 + c3;
    }
    __syncthreads();

    // ---- mainloop
    float acc[2][8][4];
    #pragma unroll
    for (int i = 0; i < 2; i++)
        #pragma unroll
        for (int j = 0; j < 8; j++)
            #pragma unroll
            for (int q = 0; q < 4; q++) acc[i][j][q] = 0.0f;

    const uint32_t lane_row = lane & 15;
    const uint32_t kb  = lane >> 4;
    const uint32_t key = lane & 7;
    const uint32_t a_base = sbase + SM_A + (warp_m * 32 + lane_row) * 256;
    const uint32_t b_base = sbase + SM_B + (warp_n * 64 + lane_row) * 256;

    #pragma unroll
    for (int k16 = 0; k16 < 8; k16++) {
        uint32_t ca = (((uint32_t)k16 * 2 + kb) ^ key) * 16;
        uint32_t a0[4], a1[4];
        ldmx4(a0, a_base + ca);
        ldmx4(a1, a_base + 4096 + ca);
        #pragma unroll
        for (int n16 = 0; n16 < 4; n16++) {
            uint32_t bf[4];
            ldmx4(bf, b_base + n16 * 4096 + ca);
            mma_bf16(acc[0][n16 * 2 + 0], a0, bf[0], bf[2]);
            mma_bf16(acc[0][n16 * 2 + 1], a0, bf[1], bf[3]);
            mma_bf16(acc[1][n16 * 2 + 0], a1, bf[0], bf[2]);
            mma_bf16(acc[1][n16 * 2 + 1], a1, bf[1], bf[3]);
        }
    }
    __syncthreads();   // A/B smem dead; colred scratch takes over

    // ---- dual-role epilogue
    float* cr = (float*)(smem + SM_A);   // [32][132]
    const int qm = lane >> 2;
    const int qn = (lane & 3) * 2;
    const int g  = warp_m * 8 + qm;
    float negLo[2] = {0.f, 0.f};
    float negHi[2] = {0.f, 0.f};

    #pragma unroll
    for (int n8 = 0; n8 < 8; n8++) {
        const int half = n8 >> 2;
        const int w = warp_n * 2 + half;
        const int p = (n8 & 3) * 8 + qn;
        const unsigned m0 = 1u << p, m1 = m0 << 1;
        const int clA = warp_n * 64 + n8 * 8 + qn;
        unsigned w2c0 = 0, w2c1 = 0;
        int pf2c0 = 0, pf2c1 = 0;
        if (offdiag) {
            w2c0 = yb2[clA * 4 + warp_m];       pf2c0 = pf2[clA * 4 + warp_m];
            w2c1 = yb2[(clA + 1) * 4 + warp_m]; pf2c1 = pf2[(clA + 1) * 4 + warp_m];
        }
        float negc0 = 0.0f, negc1 = 0.0f;
        #pragma unroll
        for (int m_i = 0; m_i < 2; m_i++) {
            const int rlo = warp_m * 32 + m_i * 16 + qm;
            const int rhi = rlo + 8;
            const unsigned wordL = yb[rlo * 4 + w];
            const unsigned wordH = yb[rhi * 4 + w];
            const int prefL = pf[rlo * 4 + w];
            const int prefH = pf[rhi * 4 + w];
            const float* d = acc[m_i][n8];
            float e0 = exp2f(d[0] * INV_T_LOG2E);
            float e1 = exp2f(d[1] * INV_T_LOG2E);
            float e2 = exp2f(d[2] * INV_T_LOG2E);
            float e3 = exp2f(d[3] * INV_T_LOG2E);
            negLo[m_i] += (wordL & m0) ? 0.0f : e0;
            negLo[m_i] += (wordL & m1) ? 0.0f : e1;
            negHi[m_i] += (wordH & m0) ? 0.0f : e2;
            negHi[m_i] += (wordH & m1) ? 0.0f : e3;
            float* gposL = g_pos + (size_t)(row0 + rlo) * POS_STRIDE + bj * BLK_POS;
            float* gposH = g_pos + (size_t)(row0 + rhi) * POS_STRIDE + bj * BLK_POS;
            if (wordL & m0) gposL[prefL + __popc(wordL & (m0 - 1))] = d[0] * INV_T;
            if (wordL & m1) gposL[prefL + __popc(wordL & (m1 - 1))] = d[1] * INV_T;
            if (wordH & m0) gposH[prefH + __popc(wordH & (m0 - 1))] = d[2] * INV_T;
            if (wordH & m1) gposH[prefH + __popc(wordH & (m1 - 1))] = d[3] * INV_T;
            if (offdiag) {
                const unsigned bL = 1u << (rlo & 31);
                const unsigned bH = 1u << (rhi & 31);
                negc0 += (w2c0 & bL) ? 0.0f : e0;
                negc0 += (w2c0 & bH) ? 0.0f : e2;
                negc1 += (w2c1 & bL) ? 0.0f : e1;
                negc1 += (w2c1 & bH) ? 0.0f : e3;
                float* gpc0 = g_pos + (size_t)(col0 + clA) * POS_STRIDE + bi * BLK_POS;
                float* gpc1 = g_pos + (size_t)(col0 + clA + 1) * POS_STRIDE + bi * BLK_POS;
                if (w2c0 & bL) gpc0[pf2c0 + __popc(w2c0 & (bL - 1))] = d[0] * INV_T;
                if (w2c0 & bH) gpc0[pf2c0 + __popc(w2c0 & (bH - 1))] = d[2] * INV_T;
                if (w2c1 & bL) gpc1[pf2c1 + __popc(w2c1 & (bL - 1))] = d[1] * INV_T;
                if (w2c1 & bH) gpc1[pf2c1 + __popc(w2c1 & (bH - 1))] = d[3] * INV_T;
            }
        }
        if (offdiag) {
            cr[g * 132 + clA]     = negc0;
            cr[g * 132 + clA + 1] = negc1;
        }
    }

    // row-role nl partials
    int slotR = bj * 2 + warp_n;
    #pragma unroll
    for (int m_i = 0; m_i < 2; m_i++) {
        float vlo = negLo[m_i], vhi = negHi[m_i];
        vlo += __shfl_xor_sync(0xFFFFFFFFu, vlo, 1);
        vlo += __shfl_xor_sync(0xFFFFFFFFu, vlo, 2);
        vhi += __shfl_xor_sync(0xFFFFFFFFu, vhi, 1);
        vhi += __shfl_xor_sync(0xFFFFFFFFu, vhi, 2);
        if ((lane & 3) == 0) {
            int r = row0 + warp_m * 32 + m_i * 16 + qm;
            g_nl_part[(size_t)r * NSLOT + slotR]       = vlo;
            g_nl_part[(size_t)(r + 8) * NSLOT + slotR] = vhi;
        }
    }

    // col-role nl reduce
    __syncthreads();
    if (offdiag && tid < 128) {
        float s = 0.0f;
        #pragma unroll
        for (int gg = 0; gg < 32; gg++) s += cr[gg * 132 + tid];
        g_nl_part[(size_t)(col0 + tid) * NSLOT + 128 + bi] = s;
    }
}

// ---------------------------------------------------------------------------
// Per-row loss + fused final reduction. 8 rows per block (one warp each).
__global__ void k_rowloss(float* __restrict__ out) {
    __shared__ float bsum[8];
    int row  = blockIdx.x * 8 + (threadIdx.x >> 5);
    int lane = threadIdx.x & 31;
    int wrp  = threadIdx.x >> 5;
    int br = row >> 7;
    const float* p = g_nl_part + (size_t)row * NSLOT;
    int lenR = 128 - 2 * br;
    int lenT = lenR + br;
    float nl = 0.0f;
    for (int i = lane; i < lenT; i += 32) {
        int s = (i < lenR) ? (2 * br + i) : (128 + (i - lenR));
        nl += p[s];
    }
    #pragma unroll
    for (int o = 16; o; o >>= 1) nl += __shfl_xor_sync(0xFFFFFFFFu, nl, o);

    const int* bc = g_bcnt + (size_t)row * 64;
    const float* ps = g_pos + (size_t)row * POS_STRIDE;
    float acc = 0.0f;
    int cnt = 0;
    #pragma unroll
    for (int bb = 0; bb < 2; bb++) {
        int b = lane + bb * 32;
        int c = bc[b];
        cnt += c;
        const float* pp = ps + b * BLK_POS;
        for (int k = 0; k < c; k++)
            acc += log1pf(nl * __expf(-pp[k]));
    }
    #pragma unroll
    for (int o = 16; o; o >>= 1) {
        acc += __shfl_xor_sync(0xFFFFFFFFu, acc, o);
        cnt += __shfl_xor_sync(0xFFFFFFFFu, cnt, o);
    }
    if (lane == 0) bsum[wrp] = acc / (float)cnt;
    __syncthreads();
    if (threadIdx.x == 0) {
        float s = 0.0f;
        #pragma unroll
        for (int i = 0; i < 8; i++) s += bsum[i];
        atomicAdd(out, s * (1.0f / (float)NN));
    }
}

// ---------------------------------------------------------------------------
extern "C" void kernel_launch(void* const* d_in, const int* in_sizes, int n_in,
                              void* d_out, int out_size) {
    const float* x = (const float*)d_in[0];
    const float* y = (const float*)d_in[1];
    float* out = (float*)d_out;

    cudaFuncSetAttribute(k_tile, cudaFuncAttributeMaxDynamicSharedMemorySize, SM_TOT);

    k_normalize<<<NN / 8, 256>>>(x, out);                // idx 0 (zeroes out)
    k_pad<<<1, 32>>>();                                  // idx 1
    k_pad<<<1, 32>>>();                                  // idx 2
    k_tile<<<NBLK, 256, SM_TOT>>>(y);                    // idx 3 (ncu slot)
    k_rowloss<<<NN / 8, 256>>>(out);                     // idx 4
}

// round 13
// speedup vs baseline: 1.3300x; 1.1076x over previous
#include <cuda_runtime.h>
#include <cuda_bf16.h>
#include <math.h>
#include <cstdint>

// ContrastiveLoss N=8192 D=128 temp=0.05 — plain-bf16 HMMA, symmetric tiles,
// fused y load, e-matrix staged to smem, bit-iteration positive extraction.
// loss = -mean_i [ (1/ppn_i) * sum_{j: y_ij=1} log( e_ij / (e_ij + nl_i) ) ]
// log(e/(e+nl)) = -log1p(nl/e), e = exp(cos/T).

#define NN 8192
#define DD 128
#define INV_T_LOG2E 28.853900817779268f   // 20 * log2(e)
#define NSLOT 192            // nl slots: row-role 0..127, col-role 128..191
#define BLK_POS 32           // positive slots per (row, 128-col block)
#define POS_STRIDE 2048      // 64 blocks * 32

__device__ __nv_bfloat16 g_xhi[NN * DD];
__device__ float g_nl_part[(size_t)NN * NSLOT];
__device__ int   g_bcnt[(size_t)NN * 64];
__device__ float g_pos[(size_t)NN * POS_STRIDE];   // holds e values

// ---------------------------------------------------------------------------
__device__ __forceinline__ uint32_t smem_u32(const void* p) {
    uint32_t a;
    asm("{ .reg .u64 t; cvta.to.shared.u64 t, %1; cvt.u32.u64 %0, t; }" : "=r"(a) : "l"(p));
    return a;
}
__device__ __forceinline__ void ldmx4(uint32_t* r, uint32_t addr) {
    asm volatile("ldmatrix.sync.aligned.m8n8.x4.shared.b16 {%0,%1,%2,%3}, [%4];"
        : "=r"(r[0]), "=r"(r[1]), "=r"(r[2]), "=r"(r[3]) : "r"(addr));
}
__device__ __forceinline__ void mma_bf16(float* d, const uint32_t* a,
                                         uint32_t b0, uint32_t b1) {
    asm volatile("mma.sync.aligned.m16n8k16.row.col.f32.bf16.bf16.f32 "
        "{%0,%1,%2,%3}, {%4,%5,%6,%7}, {%8,%9}, {%0,%1,%2,%3};"
        : "+f"(d[0]), "+f"(d[1]), "+f"(d[2]), "+f"(d[3])
        : "r"(a[0]), "r"(a[1]), "r"(a[2]), "r"(a[3]), "r"(b0), "r"(b1));
}
__device__ __forceinline__ unsigned nib4(float4 v) {
    return (unsigned)(v.x != 0.0f) | ((unsigned)(v.y != 0.0f) << 1)
         | ((unsigned)(v.z != 0.0f) << 2) | ((unsigned)(v.w != 0.0f) << 3);
}

// ---------------------------------------------------------------------------
__global__ void k_normalize(const float* __restrict__ x, float* __restrict__ out) {
    if (blockIdx.x == 0 && threadIdx.x == 0) out[0] = 0.0f;
    int row  = blockIdx.x * 8 + (threadIdx.x >> 5);
    int lane = threadIdx.x & 31;
    float4 v = ((const float4*)(x + (size_t)row * DD))[lane];
    float ss = v.x * v.x + v.y * v.y + v.z * v.z + v.w * v.w;
    #pragma unroll
    for (int o = 16; o; o >>= 1) ss += __shfl_xor_sync(0xFFFFFFFFu, ss, o);
    float inv = rsqrtf(ss);
    float f[4] = {v.x * inv, v.y * inv, v.z * inv, v.w * inv};
    ushort4 hi4;
    unsigned short* hp = &hi4.x;
    #pragma unroll
    for (int i = 0; i < 4; i++) {
        __nv_bfloat16 h = __float2bfloat16(f[i]);
        hp[i] = *(unsigned short*)&h;
    }
    ((ushort4*)(g_xhi + (size_t)row * DD))[lane] = hi4;
}

// ---------------------------------------------------------------------------
__global__ void k_pad() {}   // keeps k_tile at launch index 3 (ncu capture slot)

// ---------------------------------------------------------------------------
// SMEM: A@0(32K)+B@32K(32K) live until mainloop end; es[128][132] floats @0
// (67584B) lives in the epilogue (overlaps dead A/B). yb@67584, yb2@69632,
// cr@71680 (32x132 floats). Total 88576 -> 2 CTAs/SM.
#define SM_A   0
#define SM_B   32768
#define SM_YB  67584
#define SM_YB2 69632
#define SM_CR  71680
#define SM_TOT 88576
#define ESTRIDE 132
#define NBLK   2080          // 64*65/2

__global__ void __launch_bounds__(256, 2) k_tile(const float* __restrict__ y) {
    int bi = 0, rem = blockIdx.x;
    while (rem >= 64 - bi) { rem -= 64 - bi; bi++; }
    const int bj = bi + rem;
    const bool offdiag = (bi != bj);

    extern __shared__ char smem[];
    uint32_t sbase = smem_u32(smem);
    const int tid  = threadIdx.x;
    const int wid  = tid >> 5;
    const int lane = tid & 31;
    const int warp_m = wid >> 1;
    const int warp_n = wid & 1;
    const int row0 = bi * 128;
    const int col0 = bj * 128;

    unsigned* yb  = (unsigned*)(smem + SM_YB);
    unsigned* yb2 = (unsigned*)(smem + SM_YB2);
    float*    es  = (float*)smem;            // [128][132] after mainloop
    float*    cr  = (float*)(smem + SM_CR);  // [32][132]

    // ---- y load first (DRAM), high MLP: 8 threads/row, 4 float4 each
    {
        const int q8 = tid & 7;
        #pragma unroll
        for (int p = 0; p < 4; p++) {
            int r = p * 32 + (tid >> 3);
            const float4* yr = (const float4*)(y + (size_t)(row0 + r) * NN + col0) + q8 * 4;
            unsigned m = 0;
            #pragma unroll
            for (int k = 0; k < 4; k++) m |= nib4(yr[k]) << (k * 4);
            unsigned o = __shfl_xor_sync(0xFFFFFFFFu, m, 1);
            if (!(tid & 1)) yb[r * 4 + (q8 >> 1)] = m | (o << 16);
            if (offdiag) {
                const float4* yc = (const float4*)(y + (size_t)(col0 + r) * NN + row0) + q8 * 4;
                unsigned m2 = 0;
                #pragma unroll
                for (int k = 0; k < 4; k++) m2 |= nib4(yc[k]) << (k * 4);
                unsigned o2 = __shfl_xor_sync(0xFFFFFFFFu, m2, 1);
                if (!(tid & 1)) yb2[r * 4 + (q8 >> 1)] = m2 | (o2 << 16);
            }
        }
    }

    // ---- A/B tile loads (L2-resident bf16)
    {
        const uint4* ah = (const uint4*)(g_xhi + (size_t)row0 * DD);
        const uint4* bh = (const uint4*)(g_xhi + (size_t)col0 * DD);
        #pragma unroll
        for (int i = 0; i < 8; i++) {
            int idx = tid + i * 256;
            int r   = idx >> 4;
            int c   = idx & 15;
            uint32_t so = (uint32_t)r * 256 + (uint32_t)((c ^ (r & 7)) * 16);
            *(uint4*)(smem + SM_A + so) = ah[idx];
            *(uint4*)(smem + SM_B + so) = bh[idx];
        }
    }
    __syncthreads();

    // ---- mainloop
    float acc[2][8][4];
    #pragma unroll
    for (int i = 0; i < 2; i++)
        #pragma unroll
        for (int j = 0; j < 8; j++)
            #pragma unroll
            for (int q = 0; q < 4; q++) acc[i][j][q] = 0.0f;

    const uint32_t lane_row = lane & 15;
    const uint32_t kb  = lane >> 4;
    const uint32_t key = lane & 7;
    const uint32_t a_base = sbase + SM_A + (warp_m * 32 + lane_row) * 256;
    const uint32_t b_base = sbase + SM_B + (warp_n * 64 + lane_row) * 256;

    #pragma unroll
    for (int k16 = 0; k16 < 8; k16++) {
        uint32_t ca = (((uint32_t)k16 * 2 + kb) ^ key) * 16;
        uint32_t a0[4], a1[4];
        ldmx4(a0, a_base + ca);
        ldmx4(a1, a_base + 4096 + ca);
        #pragma unroll
        for (int n16 = 0; n16 < 4; n16++) {
            uint32_t bf[4];
            ldmx4(bf, b_base + n16 * 4096 + ca);
            mma_bf16(acc[0][n16 * 2 + 0], a0, bf[0], bf[2]);
            mma_bf16(acc[0][n16 * 2 + 1], a0, bf[1], bf[3]);
            mma_bf16(acc[1][n16 * 2 + 0], a1, bf[0], bf[2]);
            mma_bf16(acc[1][n16 * 2 + 1], a1, bf[1], bf[3]);
        }
    }
    __syncthreads();   // A/B smem dead; es takes over

    // ---- epilogue phase 1: exp + neg accumulation + STS e-matrix
    const int qm = lane >> 2;
    const int qn = (lane & 3) * 2;
    float negLo[2] = {0.f, 0.f};
    float negHi[2] = {0.f, 0.f};

    #pragma unroll
    for (int n8 = 0; n8 < 8; n8++) {
        const int half = n8 >> 2;
        const int w = warp_n * 2 + half;
        const int p = (n8 & 3) * 8 + qn;
        const unsigned m0 = 1u << p, m1 = m0 << 1;
        const int clA = warp_n * 64 + n8 * 8 + qn;
        unsigned w2c0 = 0, w2c1 = 0;
        if (offdiag) {
            w2c0 = yb2[clA * 4 + warp_m];
            w2c1 = yb2[(clA + 1) * 4 + warp_m];
        }
        float negc0 = 0.0f, negc1 = 0.0f;
        #pragma unroll
        for (int m_i = 0; m_i < 2; m_i++) {
            const int rlo = warp_m * 32 + m_i * 16 + qm;
            const int rhi = rlo + 8;
            const unsigned wordL = yb[rlo * 4 + w];
            const unsigned wordH = yb[rhi * 4 + w];
            const float* d = acc[m_i][n8];
            float e0 = exp2f(d[0] * INV_T_LOG2E);
            float e1 = exp2f(d[1] * INV_T_LOG2E);
            float e2 = exp2f(d[2] * INV_T_LOG2E);
            float e3 = exp2f(d[3] * INV_T_LOG2E);
            negLo[m_i] += (wordL & m0) ? 0.0f : e0;
            negLo[m_i] += (wordL & m1) ? 0.0f : e1;
            negHi[m_i] += (wordH & m0) ? 0.0f : e2;
            negHi[m_i] += (wordH & m1) ? 0.0f : e3;
            *(float2*)(es + rlo * ESTRIDE + clA) = make_float2(e0, e1);
            *(float2*)(es + rhi * ESTRIDE + clA) = make_float2(e2, e3);
            if (offdiag) {
                const unsigned bL = 1u << (rlo & 31);
                const unsigned bH = 1u << (rhi & 31);
                negc0 += (w2c0 & bL) ? 0.0f : e0;
                negc0 += (w2c0 & bH) ? 0.0f : e2;
                negc1 += (w2c1 & bL) ? 0.0f : e1;
                negc1 += (w2c1 & bH) ? 0.0f : e3;
            }
        }
        if (offdiag) {
            cr[(warp_m * 8 + qm) * ESTRIDE + clA]     = negc0;
            cr[(warp_m * 8 + qm) * ESTRIDE + clA + 1] = negc1;
        }
    }

    // row-role nl partials
    int slotR = bj * 2 + warp_n;
    #pragma unroll
    for (int m_i = 0; m_i < 2; m_i++) {
        float vlo = negLo[m_i], vhi = negHi[m_i];
        vlo += __shfl_xor_sync(0xFFFFFFFFu, vlo, 1);
        vlo += __shfl_xor_sync(0xFFFFFFFFu, vlo, 2);
        vhi += __shfl_xor_sync(0xFFFFFFFFu, vhi, 1);
        vhi += __shfl_xor_sync(0xFFFFFFFFu, vhi, 2);
        if ((lane & 3) == 0) {
            int r = row0 + warp_m * 32 + m_i * 16 + qm;
            g_nl_part[(size_t)r * NSLOT + slotR]       = vlo;
            g_nl_part[(size_t)(r + 8) * NSLOT + slotR] = vhi;
        }
    }

    __syncthreads();

    // ---- epilogue phase 2: col nl reduce + sparse positive extraction
    if (tid < 128) {
        if (offdiag) {
            float s = 0.0f;
            #pragma unroll
            for (int gg = 0; gg < 32; gg++) s += cr[gg * ESTRIDE + tid];
            g_nl_part[(size_t)(col0 + tid) * NSLOT + 128 + bi] = s;
        }
        // row-role positives: row tid
        float* gp = g_pos + (size_t)(row0 + tid) * POS_STRIDE + bj * BLK_POS;
        int k = 0;
        #pragma unroll
        for (int w = 0; w < 4; w++) {
            unsigned word = yb[tid * 4 + w];
            while (word) {
                int b = __ffs(word) - 1;
                word &= word - 1;
                gp[k++] = es[tid * ESTRIDE + w * 32 + b];
            }
        }
        g_bcnt[(size_t)(row0 + tid) * 64 + bj] = k;
    } else if (offdiag) {
        // col-role positives: column c (transposed read of es)
        int c = tid - 128;
        float* gp = g_pos + (size_t)(col0 + c) * POS_STRIDE + bi * BLK_POS;
        int k = 0;
        #pragma unroll
        for (int w = 0; w < 4; w++) {
            unsigned word = yb2[c * 4 + w];
            while (word) {
                int b = __ffs(word) - 1;
                word &= word - 1;
                gp[k++] = es[(w * 32 + b) * ESTRIDE + c];
            }
        }
        g_bcnt[(size_t)(col0 + c) * 64 + bi] = k;
    }
}

// ---------------------------------------------------------------------------
// Per-row loss + fused final reduction. g_pos holds e values:
// contribution = log1p(nl / e).
__global__ void k_rowloss(float* __restrict__ out) {
    __shared__ float bsum[8];
    int row  = blockIdx.x * 8 + (threadIdx.x >> 5);
    int lane = threadIdx.x & 31;
    int wrp  = threadIdx.x >> 5;
    int br = row >> 7;
    const float* p = g_nl_part + (size_t)row * NSLOT;
    int lenR = 128 - 2 * br;
    int lenT = lenR + br;
    float nl = 0.0f;
    for (int i = lane; i < lenT; i += 32) {
        int s = (i < lenR) ? (2 * br + i) : (128 + (i - lenR));
        nl += p[s];
    }
    #pragma unroll
    for (int o = 16; o; o >>= 1) nl += __shfl_xor_sync(0xFFFFFFFFu, nl, o);

    const int* bc = g_bcnt + (size_t)row * 64;
    const float* ps = g_pos + (size_t)row * POS_STRIDE;
    float acc = 0.0f;
    int cnt = 0;
    #pragma unroll
    for (int bb = 0; bb < 2; bb++) {
        int b = lane + bb * 32;
        int c = bc[b];
        cnt += c;
        const float* pp = ps + b * BLK_POS;
        for (int k = 0; k < c; k++)
            acc += log1pf(__fdividef(nl, pp[k]));
    }
    #pragma unroll
    for (int o = 16; o; o >>= 1) {
        acc += __shfl_xor_sync(0xFFFFFFFFu, acc, o);
        cnt += __shfl_xor_sync(0xFFFFFFFFu, cnt, o);
    }
    if (lane == 0) bsum[wrp] = acc / (float)cnt;
    __syncthreads();
    if (threadIdx.x == 0) {
        float s = 0.0f;
        #pragma unroll
        for (int i = 0; i < 8; i++) s += bsum[i];
        atomicAdd(out, s * (1.0f / (float)NN));
    }
}

// ---------------------------------------------------------------------------
extern "C" void kernel_launch(void* const* d_in, const int* in_sizes, int n_in,
                              void* d_out, int out_size) {
    const float* x = (const float*)d_in[0];
    const float* y = (const float*)d_in[1];
    float* out = (float*)d_out;

    cudaFuncSetAttribute(k_tile, cudaFuncAttributeMaxDynamicSharedMemorySize, SM_TOT);

    k_normalize<<<NN / 8, 256>>>(x, out);                // idx 0 (zeroes out)
    k_pad<<<1, 32>>>();                                  // idx 1
    k_pad<<<1, 32>>>();                                  // idx 2
    k_tile<<<NBLK, 256, SM_TOT>>>(y);                    // idx 3 (ncu slot)
    k_rowloss<<<NN / 8, 256>>>(out);                     // idx 4
}

// round 14
// speedup vs baseline: 1.3709x; 1.0307x over previous
#include <cuda_runtime.h>
#include <cuda_bf16.h>
#include <math.h>
#include <cstdint>

// ContrastiveLoss N=8192 D=128 temp=0.05 — plain-bf16 HMMA, symmetric tiles,
// fused y load, maskless epilogue (nl = total - posSum, diagonal excluded),
// bf16 e-matrix staging, bit-iteration positive extraction.
// loss = -mean_i [ (1/ppn_i) * sum_{j: y_ij=1} log( e_ij / (e_ij + nl_i) ) ]
// log(e/(e+nl)) = -log1p(nl/e), e = exp(cos/T).

#define NN 8192
#define DD 128
#define INV_T_LOG2E 28.853900817779268f   // 20 * log2(e)
#define NSLOT 128            // nl slots: row-role bj (0..63), col-role 64+bi
#define BLK_POS 32           // positive slots per (row, 128-col block)
#define POS_STRIDE 2048      // 64 blocks * 32

__device__ __nv_bfloat16 g_xhi[NN * DD];
__device__ float g_nl_part[(size_t)NN * NSLOT];
__device__ int   g_bcnt[(size_t)NN * 64];
__device__ float g_pos[(size_t)NN * POS_STRIDE];   // holds e values

// ---------------------------------------------------------------------------
__device__ __forceinline__ uint32_t smem_u32(const void* p) {
    uint32_t a;
    asm("{ .reg .u64 t; cvta.to.shared.u64 t, %1; cvt.u32.u64 %0, t; }" : "=r"(a) : "l"(p));
    return a;
}
__device__ __forceinline__ void ldmx4(uint32_t* r, uint32_t addr) {
    asm volatile("ldmatrix.sync.aligned.m8n8.x4.shared.b16 {%0,%1,%2,%3}, [%4];"
        : "=r"(r[0]), "=r"(r[1]), "=r"(r[2]), "=r"(r[3]) : "r"(addr));
}
__device__ __forceinline__ void mma_bf16(float* d, const uint32_t* a,
                                         uint32_t b0, uint32_t b1) {
    asm volatile("mma.sync.aligned.m16n8k16.row.col.f32.bf16.bf16.f32 "
        "{%0,%1,%2,%3}, {%4,%5,%6,%7}, {%8,%9}, {%0,%1,%2,%3};"
        : "+f"(d[0]), "+f"(d[1]), "+f"(d[2]), "+f"(d[3])
        : "r"(a[0]), "r"(a[1]), "r"(a[2]), "r"(a[3]), "r"(b0), "r"(b1));
}
__device__ __forceinline__ unsigned nib4(float4 v) {
    return (unsigned)(v.x != 0.0f) | ((unsigned)(v.y != 0.0f) << 1)
         | ((unsigned)(v.z != 0.0f) << 2) | ((unsigned)(v.w != 0.0f) << 3);
}

// ---------------------------------------------------------------------------
__global__ void k_normalize(const float* __restrict__ x, float* __restrict__ out) {
    if (blockIdx.x == 0 && threadIdx.x == 0) out[0] = 0.0f;
    int row  = blockIdx.x * 8 + (threadIdx.x >> 5);
    int lane = threadIdx.x & 31;
    float4 v = ((const float4*)(x + (size_t)row * DD))[lane];
    float ss = v.x * v.x + v.y * v.y + v.z * v.z + v.w * v.w;
    #pragma unroll
    for (int o = 16; o; o >>= 1) ss += __shfl_xor_sync(0xFFFFFFFFu, ss, o);
    float inv = rsqrtf(ss);
    float f[4] = {v.x * inv, v.y * inv, v.z * inv, v.w * inv};
    ushort4 hi4;
    unsigned short* hp = &hi4.x;
    #pragma unroll
    for (int i = 0; i < 4; i++) {
        __nv_bfloat16 h = __float2bfloat16(f[i]);
        hp[i] = *(unsigned short*)&h;
    }
    ((ushort4*)(g_xhi + (size_t)row * DD))[lane] = hi4;
}

// ---------------------------------------------------------------------------
__global__ void k_pad() {}   // keeps k_tile at launch index 3 (ncu capture slot)

// ---------------------------------------------------------------------------
// SMEM: A@0(32K)+B@32K(32K) live until mainloop; epilogue overlay in [0,64K):
//   es bf16 [128][132] @0 (33792B), cr float [32][132] @33792 (16896B),
//   rt float [128][2] @50688 (1024B). yb@65536 (2K), yb2@67584 (2K).
#define SM_A   0
#define SM_B   32768
#define SM_CR  33792
#define SM_RT  50688
#define SM_YB  65536
#define SM_YB2 67584
#define SM_TOT 69632
#define ESTRIDE 132
#define NBLK   2080          // 64*65/2

__global__ void __launch_bounds__(256, 2) k_tile(const float* __restrict__ y) {
    int bi = 0, rem = blockIdx.x;
    while (rem >= 64 - bi) { rem -= 64 - bi; bi++; }
    const int bj = bi + rem;
    const bool offdiag = (bi != bj);

    extern __shared__ char smem[];
    uint32_t sbase = smem_u32(smem);
    const int tid  = threadIdx.x;
    const int wid  = tid >> 5;
    const int lane = tid & 31;
    const int warp_m = wid >> 1;
    const int warp_n = wid & 1;
    const int row0 = bi * 128;
    const int col0 = bj * 128;

    unsigned* yb  = (unsigned*)(smem + SM_YB);
    unsigned* yb2 = (unsigned*)(smem + SM_YB2);
    __nv_bfloat16* es = (__nv_bfloat16*)smem;    // after mainloop
    float* cr = (float*)(smem + SM_CR);
    float* rt = (float*)(smem + SM_RT);

    // ---- y load first (DRAM), high MLP: 8 threads/row, 4 float4 each
    {
        const int q8 = tid & 7;
        #pragma unroll
        for (int p = 0; p < 4; p++) {
            int r = p * 32 + (tid >> 3);
            const float4* yr = (const float4*)(y + (size_t)(row0 + r) * NN + col0) + q8 * 4;
            unsigned m = 0;
            #pragma unroll
            for (int k = 0; k < 4; k++) m |= nib4(yr[k]) << (k * 4);
            unsigned o = __shfl_xor_sync(0xFFFFFFFFu, m, 1);
            if (!(tid & 1)) yb[r * 4 + (q8 >> 1)] = m | (o << 16);
            if (offdiag) {
                const float4* yc = (const float4*)(y + (size_t)(col0 + r) * NN + row0) + q8 * 4;
                unsigned m2 = 0;
                #pragma unroll
                for (int k = 0; k < 4; k++) m2 |= nib4(yc[k]) << (k * 4);
                unsigned o2 = __shfl_xor_sync(0xFFFFFFFFu, m2, 1);
                if (!(tid & 1)) yb2[r * 4 + (q8 >> 1)] = m2 | (o2 << 16);
            }
        }
    }

    // ---- A/B tile loads (L2-resident bf16)
    {
        const uint4* ah = (const uint4*)(g_xhi + (size_t)row0 * DD);
        const uint4* bh = (const uint4*)(g_xhi + (size_t)col0 * DD);
        #pragma unroll
        for (int i = 0; i < 8; i++) {
            int idx = tid + i * 256;
            int r   = idx >> 4;
            int c   = idx & 15;
            uint32_t so = (uint32_t)r * 256 + (uint32_t)((c ^ (r & 7)) * 16);
            *(uint4*)(smem + SM_A + so) = ah[idx];
            *(uint4*)(smem + SM_B + so) = bh[idx];
        }
    }
    __syncthreads();

    // ---- mainloop
    float acc[2][8][4];
    #pragma unroll
    for (int i = 0; i < 2; i++)
        #pragma unroll
        for (int j = 0; j < 8; j++)
            #pragma unroll
            for (int q = 0; q < 4; q++) acc[i][j][q] = 0.0f;

    const uint32_t lane_row = lane & 15;
    const uint32_t kb  = lane >> 4;
    const uint32_t key = lane & 7;
    const uint32_t a_base = sbase + SM_A + (warp_m * 32 + lane_row) * 256;
    const uint32_t b_base = sbase + SM_B + (warp_n * 64 + lane_row) * 256;

    #pragma unroll
    for (int k16 = 0; k16 < 8; k16++) {
        uint32_t ca = (((uint32_t)k16 * 2 + kb) ^ key) * 16;
        uint32_t a0[4], a1[4];
        ldmx4(a0, a_base + ca);
        ldmx4(a1, a_base + 4096 + ca);
        #pragma unroll
        for (int n16 = 0; n16 < 4; n16++) {
            uint32_t bf[4];
            ldmx4(bf, b_base + n16 * 4096 + ca);
            mma_bf16(acc[0][n16 * 2 + 0], a0, bf[0], bf[2]);
            mma_bf16(acc[0][n16 * 2 + 1], a0, bf[1], bf[3]);
            mma_bf16(acc[1][n16 * 2 + 0], a1, bf[0], bf[2]);
            mma_bf16(acc[1][n16 * 2 + 1], a1, bf[1], bf[3]);
        }
    }
    __syncthreads();   // A/B smem dead; es/cr/rt overlay takes over

    // ---- epilogue phase 1: maskless totals + bf16 e staging
    const int qm = lane >> 2;
    const int qn = (lane & 3) * 2;
    const int g  = warp_m * 8 + qm;
    float totLo[2] = {0.f, 0.f};
    float totHi[2] = {0.f, 0.f};

    if (offdiag) {
        #pragma unroll
        for (int n8 = 0; n8 < 8; n8++) {
            const int clA = warp_n * 64 + n8 * 8 + qn;
            float negc0 = 0.0f, negc1 = 0.0f;
            #pragma unroll
            for (int m_i = 0; m_i < 2; m_i++) {
                const int rlo = warp_m * 32 + m_i * 16 + qm;
                const int rhi = rlo + 8;
                const float* d = acc[m_i][n8];
                float e0 = exp2f(d[0] * INV_T_LOG2E);
                float e1 = exp2f(d[1] * INV_T_LOG2E);
                float e2 = exp2f(d[2] * INV_T_LOG2E);
                float e3 = exp2f(d[3] * INV_T_LOG2E);
                totLo[m_i] += e0 + e1;
                totHi[m_i] += e2 + e3;
                negc0 += e0 + e2;
                negc1 += e1 + e3;
                *(__nv_bfloat162*)(es + rlo * ESTRIDE + clA) = __floats2bfloat162_rn(e0, e1);
                *(__nv_bfloat162*)(es + rhi * ESTRIDE + clA) = __floats2bfloat162_rn(e2, e3);
            }
            cr[g * ESTRIDE + clA]     = negc0;
            cr[g * ESTRIDE + clA + 1] = negc1;
        }
    } else {
        // diagonal tile: zero the (known-positive) diagonal out of totals
        #pragma unroll
        for (int n8 = 0; n8 < 8; n8++) {
            const int clA = warp_n * 64 + n8 * 8 + qn;
            #pragma unroll
            for (int m_i = 0; m_i < 2; m_i++) {
                const int rlo = warp_m * 32 + m_i * 16 + qm;
                const int rhi = rlo + 8;
                const float* d = acc[m_i][n8];
                float e0 = exp2f(d[0] * INV_T_LOG2E);
                float e1 = exp2f(d[1] * INV_T_LOG2E);
                float e2 = exp2f(d[2] * INV_T_LOG2E);
                float e3 = exp2f(d[3] * INV_T_LOG2E);
                totLo[m_i] += ((rlo != clA)     ? e0 : 0.0f)
                            + ((rlo != clA + 1) ? e1 : 0.0f);
                totHi[m_i] += ((rhi != clA)     ? e2 : 0.0f)
                            + ((rhi != clA + 1) ? e3 : 0.0f);
                *(__nv_bfloat162*)(es + rlo * ESTRIDE + clA) = __floats2bfloat162_rn(e0, e1);
                *(__nv_bfloat162*)(es + rhi * ESTRIDE + clA) = __floats2bfloat162_rn(e2, e3);
            }
        }
    }

    // reduce row totals across the 4 col-lanes, stage to rt[row][warp_n]
    #pragma unroll
    for (int m_i = 0; m_i < 2; m_i++) {
        float vlo = totLo[m_i], vhi = totHi[m_i];
        vlo += __shfl_xor_sync(0xFFFFFFFFu, vlo, 1);
        vlo += __shfl_xor_sync(0xFFFFFFFFu, vlo, 2);
        vhi += __shfl_xor_sync(0xFFFFFFFFu, vhi, 1);
        vhi += __shfl_xor_sync(0xFFFFFFFFu, vhi, 2);
        if ((lane & 3) == 0) {
            int r = warp_m * 32 + m_i * 16 + qm;
            rt[r * 2 + warp_n]       = vlo;
            rt[(r + 8) * 2 + warp_n] = vhi;
        }
    }
    __syncthreads();

    // ---- epilogue phase 2: sparse extraction + nl = total - posSum
    if (tid < 128) {
        int r = tid;
        float tot = rt[r * 2] + rt[r * 2 + 1];
        float* gp = g_pos + (size_t)(row0 + r) * POS_STRIDE + bj * BLK_POS;
        float posSum = 0.0f;
        int k = 0;
        #pragma unroll
        for (int w = 0; w < 4; w++) {
            unsigned word = yb[r * 4 + w];
            while (word) {
                int b = __ffs(word) - 1;
                word &= word - 1;
                int cc = w * 32 + b;
                float e = __bfloat162float(es[r * ESTRIDE + cc]);
                gp[k++] = e;
                posSum += (offdiag || cc != r) ? e : 0.0f;
            }
        }
        g_bcnt[(size_t)(row0 + r) * 64 + bj] = k;
        g_nl_part[(size_t)(row0 + r) * NSLOT + bj] = tot - posSum;
    } else if (offdiag) {
        int c = tid - 128;
        float tot = 0.0f;
        #pragma unroll
        for (int gg = 0; gg < 32; gg++) tot += cr[gg * ESTRIDE + c];
        float* gp = g_pos + (size_t)(col0 + c) * POS_STRIDE + bi * BLK_POS;
        float posSum = 0.0f;
        int k = 0;
        #pragma unroll
        for (int w = 0; w < 4; w++) {
            unsigned word = yb2[c * 4 + w];
            while (word) {
                int b = __ffs(word) - 1;
                word &= word - 1;
                float e = __bfloat162float(es[(w * 32 + b) * ESTRIDE + c]);
                gp[k++] = e;
                posSum += e;
            }
        }
        g_bcnt[(size_t)(col0 + c) * 64 + bi] = k;
        g_nl_part[(size_t)(col0 + c) * NSLOT + 64 + bi] = tot - posSum;
    }
}

// ---------------------------------------------------------------------------
// Per-row loss + fused final reduction. Row in block br has exactly 64 valid
// nl slots: row-role [br,64), col-role [64, 64+br). g_pos holds e values.
__global__ void k_rowloss(float* __restrict__ out) {
    __shared__ float bsum[8];
    int row  = blockIdx.x * 8 + (threadIdx.x >> 5);
    int lane = threadIdx.x & 31;
    int wrp  = threadIdx.x >> 5;
    int br = row >> 7;
    const float* p = g_nl_part + (size_t)row * NSLOT;
    float nl = 0.0f;
    #pragma unroll
    for (int bb = 0; bb < 2; bb++) {
        int i = lane + bb * 32;
        int s = (i < 64 - br) ? (br + i) : (64 + i - (64 - br));
        nl += p[s];
    }
    #pragma unroll
    for (int o = 16; o; o >>= 1) nl += __shfl_xor_sync(0xFFFFFFFFu, nl, o);

    const int* bc = g_bcnt + (size_t)row * 64;
    const float* ps = g_pos + (size_t)row * POS_STRIDE;
    float acc = 0.0f;
    int cnt = 0;
    #pragma unroll
    for (int bb = 0; bb < 2; bb++) {
        int b = lane + bb * 32;
        int c = bc[b];
        cnt += c;
        const float* pp = ps + b * BLK_POS;
        for (int k = 0; k < c; k++)
            acc += log1pf(__fdividef(nl, pp[k]));
    }
    #pragma unroll
    for (int o = 16; o; o >>= 1) {
        acc += __shfl_xor_sync(0xFFFFFFFFu, acc, o);
        cnt += __shfl_xor_sync(0xFFFFFFFFu, cnt, o);
    }
    if (lane == 0) bsum[wrp] = acc / (float)cnt;
    __syncthreads();
    if (threadIdx.x == 0) {
        float s = 0.0f;
        #pragma unroll
        for (int i = 0; i < 8; i++) s += bsum[i];
        atomicAdd(out, s * (1.0f / (float)NN));
    }
}

// ---------------------------------------------------------------------------
extern "C" void kernel_launch(void* const* d_in, const int* in_sizes, int n_in,
                              void* d_out, int out_size) {
    const float* x = (const float*)d_in[0];
    const float* y = (const float*)d_in[1];
    float* out = (float*)d_out;

    cudaFuncSetAttribute(k_tile, cudaFuncAttributeMaxDynamicSharedMemorySize, SM_TOT);

    k_normalize<<<NN / 8, 256>>>(x, out);                // idx 0 (zeroes out)
    k_pad<<<1, 32>>>();                                  // idx 1
    k_pad<<<1, 32>>>();                                  // idx 2
    k_tile<<<NBLK, 256, SM_TOT>>>(y);                    // idx 3 (ncu slot)
    k_rowloss<<<NN / 8, 256>>>(out);                     // idx 4
}

// round 15
// speedup vs baseline: 1.3912x; 1.0149x over previous
#include <cuda_runtime.h>
#include <cuda_bf16.h>
#include <math.h>
#include <cstdint>

// ContrastiveLoss N=8192 D=128 temp=0.05 — plain-bf16 HMMA, symmetric tiles,
// 512-thread CTAs (16 warps, 32x32 warp tiles) for 2x occupancy,
// fused y load, maskless epilogue (nl = total - posSum), bf16 e staging.
// loss = -mean_i [ (1/ppn_i) * sum_{j: y_ij=1} log( e_ij / (e_ij + nl_i) ) ]
// log(e/(e+nl)) = -log1p(nl/e), e = exp(cos/T).

#define NN 8192
#define DD 128
#define INV_T_LOG2E 28.853900817779268f   // 20 * log2(e)
#define NSLOT 128            // nl slots: row-role bj (0..63), col-role 64+bi
#define BLK_POS 32           // positive slots per (row, 128-col block)
#define POS_STRIDE 2048      // 64 blocks * 32

__device__ __nv_bfloat16 g_xhi[NN * DD];
__device__ float g_nl_part[(size_t)NN * NSLOT];
__device__ int   g_bcnt[(size_t)NN * 64];
__device__ float g_pos[(size_t)NN * POS_STRIDE];   // holds e values

// ---------------------------------------------------------------------------
__device__ __forceinline__ uint32_t smem_u32(const void* p) {
    uint32_t a;
    asm("{ .reg .u64 t; cvta.to.shared.u64 t, %1; cvt.u32.u64 %0, t; }" : "=r"(a) : "l"(p));
    return a;
}
__device__ __forceinline__ void ldmx4(uint32_t* r, uint32_t addr) {
    asm volatile("ldmatrix.sync.aligned.m8n8.x4.shared.b16 {%0,%1,%2,%3}, [%4];"
        : "=r"(r[0]), "=r"(r[1]), "=r"(r[2]), "=r"(r[3]) : "r"(addr));
}
__device__ __forceinline__ void mma_bf16(float* d, const uint32_t* a,
                                         uint32_t b0, uint32_t b1) {
    asm volatile("mma.sync.aligned.m16n8k16.row.col.f32.bf16.bf16.f32 "
        "{%0,%1,%2,%3}, {%4,%5,%6,%7}, {%8,%9}, {%0,%1,%2,%3};"
        : "+f"(d[0]), "+f"(d[1]), "+f"(d[2]), "+f"(d[3])
        : "r"(a[0]), "r"(a[1]), "r"(a[2]), "r"(a[3]), "r"(b0), "r"(b1));
}
__device__ __forceinline__ unsigned nib4(float4 v) {
    return (unsigned)(v.x != 0.0f) | ((unsigned)(v.y != 0.0f) << 1)
         | ((unsigned)(v.z != 0.0f) << 2) | ((unsigned)(v.w != 0.0f) << 3);
}

// ---------------------------------------------------------------------------
__global__ void k_normalize(const float* __restrict__ x, float* __restrict__ out) {
    if (blockIdx.x == 0 && threadIdx.x == 0) out[0] = 0.0f;
    int row  = blockIdx.x * 8 + (threadIdx.x >> 5);
    int lane = threadIdx.x & 31;
    float4 v = ((const float4*)(x + (size_t)row * DD))[lane];
    float ss = v.x * v.x + v.y * v.y + v.z * v.z + v.w * v.w;
    #pragma unroll
    for (int o = 16; o; o >>= 1) ss += __shfl_xor_sync(0xFFFFFFFFu, ss, o);
    float inv = rsqrtf(ss);
    float f[4] = {v.x * inv, v.y * inv, v.z * inv, v.w * inv};
    ushort4 hi4;
    unsigned short* hp = &hi4.x;
    #pragma unroll
    for (int i = 0; i < 4; i++) {
        __nv_bfloat16 h = __float2bfloat16(f[i]);
        hp[i] = *(unsigned short*)&h;
    }
    ((ushort4*)(g_xhi + (size_t)row * DD))[lane] = hi4;
}

// ---------------------------------------------------------------------------
__global__ void k_pad() {}   // keeps k_tile at launch index 3 (ncu capture slot)

// ---------------------------------------------------------------------------
// SMEM: A@0(32K)+B@32K(32K) until mainloop end; epilogue overlay in [0,64K):
//   es bf16 [128][132] @0 (33792B), cr float [32][132] @33792 (16896B),
//   rt float [128][4] @50688 (2048B). yb@65536 (2K), yb2@67584 (2K).
#define SM_A   0
#define SM_B   32768
#define SM_CR  33792
#define SM_RT  50688
#define SM_YB  65536
#define SM_YB2 67584
#define SM_TOT 69632
#define ESTRIDE 132
#define NBLK   2080          // 64*65/2

__global__ void __launch_bounds__(512, 2) k_tile(const float* __restrict__ y) {
    int bi = 0, rem = blockIdx.x;
    while (rem >= 64 - bi) { rem -= 64 - bi; bi++; }
    const int bj = bi + rem;
    const bool offdiag = (bi != bj);

    extern __shared__ char smem[];
    uint32_t sbase = smem_u32(smem);
    const int tid  = threadIdx.x;
    const int wid  = tid >> 5;       // 0..15
    const int lane = tid & 31;
    const int warp_m = wid >> 2;     // 0..3 (32 rows)
    const int warp_n = wid & 3;      // 0..3 (32 cols)
    const int row0 = bi * 128;
    const int col0 = bj * 128;

    unsigned* yb  = (unsigned*)(smem + SM_YB);
    unsigned* yb2 = (unsigned*)(smem + SM_YB2);
    __nv_bfloat16* es = (__nv_bfloat16*)smem;    // after mainloop
    float* cr = (float*)(smem + SM_CR);
    float* rt = (float*)(smem + SM_RT);

    // ---- y load first (DRAM), high MLP: 8 threads/row, 4 float4 each
    {
        const int q8 = tid & 7;
        #pragma unroll
        for (int p = 0; p < 2; p++) {
            int r = p * 64 + (tid >> 3);
            const float4* yr = (const float4*)(y + (size_t)(row0 + r) * NN + col0) + q8 * 4;
            unsigned m = 0;
            #pragma unroll
            for (int k = 0; k < 4; k++) m |= nib4(yr[k]) << (k * 4);
            unsigned o = __shfl_xor_sync(0xFFFFFFFFu, m, 1);
            if (!(tid & 1)) yb[r * 4 + (q8 >> 1)] = m | (o << 16);
            if (offdiag) {
                const float4* yc = (const float4*)(y + (size_t)(col0 + r) * NN + row0) + q8 * 4;
                unsigned m2 = 0;
                #pragma unroll
                for (int k = 0; k < 4; k++) m2 |= nib4(yc[k]) << (k * 4);
                unsigned o2 = __shfl_xor_sync(0xFFFFFFFFu, m2, 1);
                if (!(tid & 1)) yb2[r * 4 + (q8 >> 1)] = m2 | (o2 << 16);
            }
        }
    }

    // ---- A/B tile loads (L2-resident bf16)
    {
        const uint4* ah = (const uint4*)(g_xhi + (size_t)row0 * DD);
        const uint4* bh = (const uint4*)(g_xhi + (size_t)col0 * DD);
        #pragma unroll
        for (int i = 0; i < 4; i++) {
            int idx = tid + i * 512;
            int r   = idx >> 4;
            int c   = idx & 15;
            uint32_t so = (uint32_t)r * 256 + (uint32_t)((c ^ (r & 7)) * 16);
            *(uint4*)(smem + SM_A + so) = ah[idx];
            *(uint4*)(smem + SM_B + so) = bh[idx];
        }
    }
    __syncthreads();

    // ---- mainloop: 32x32 warp tile, 64 MMAs/warp
    float acc[2][4][4];
    #pragma unroll
    for (int i = 0; i < 2; i++)
        #pragma unroll
        for (int j = 0; j < 4; j++)
            #pragma unroll
            for (int q = 0; q < 4; q++) acc[i][j][q] = 0.0f;

    const uint32_t lane_row = lane & 15;
    const uint32_t kb  = lane >> 4;
    const uint32_t key = lane & 7;
    const uint32_t a_base = sbase + SM_A + (warp_m * 32 + lane_row) * 256;
    const uint32_t b_base = sbase + SM_B + (warp_n * 32 + lane_row) * 256;

    #pragma unroll
    for (int k16 = 0; k16 < 8; k16++) {
        uint32_t ca = (((uint32_t)k16 * 2 + kb) ^ key) * 16;
        uint32_t a0[4], a1[4], b0[4], b1[4];
        ldmx4(a0, a_base + ca);
        ldmx4(a1, a_base + 4096 + ca);
        ldmx4(b0, b_base + ca);
        ldmx4(b1, b_base + 4096 + ca);
        mma_bf16(acc[0][0], a0, b0[0], b0[2]);
        mma_bf16(acc[0][1], a0, b0[1], b0[3]);
        mma_bf16(acc[0][2], a0, b1[0], b1[2]);
        mma_bf16(acc[0][3], a0, b1[1], b1[3]);
        mma_bf16(acc[1][0], a1, b0[0], b0[2]);
        mma_bf16(acc[1][1], a1, b0[1], b0[3]);
        mma_bf16(acc[1][2], a1, b1[0], b1[2]);
        mma_bf16(acc[1][3], a1, b1[1], b1[3]);
    }
    __syncthreads();   // A/B smem dead; es/cr/rt overlay takes over

    // ---- epilogue phase 1: maskless totals + bf16 e staging
    const int qm = lane >> 2;
    const int qn = (lane & 3) * 2;
    const int g  = warp_m * 8 + qm;
    float totLo[2] = {0.f, 0.f};
    float totHi[2] = {0.f, 0.f};

    if (offdiag) {
        #pragma unroll
        for (int n8 = 0; n8 < 4; n8++) {
            const int clA = warp_n * 32 + n8 * 8 + qn;
            float negc0 = 0.0f, negc1 = 0.0f;
            #pragma unroll
            for (int m_i = 0; m_i < 2; m_i++) {
                const int rlo = warp_m * 32 + m_i * 16 + qm;
                const int rhi = rlo + 8;
                const float* d = acc[m_i][n8];
                float e0 = exp2f(d[0] * INV_T_LOG2E);
                float e1 = exp2f(d[1] * INV_T_LOG2E);
                float e2 = exp2f(d[2] * INV_T_LOG2E);
                float e3 = exp2f(d[3] * INV_T_LOG2E);
                totLo[m_i] += e0 + e1;
                totHi[m_i] += e2 + e3;
                negc0 += e0 + e2;
                negc1 += e1 + e3;
                *(__nv_bfloat162*)(es + rlo * ESTRIDE + clA) = __floats2bfloat162_rn(e0, e1);
                *(__nv_bfloat162*)(es + rhi * ESTRIDE + clA) = __floats2bfloat162_rn(e2, e3);
            }
            cr[g * ESTRIDE + clA]     = negc0;
            cr[g * ESTRIDE + clA + 1] = negc1;
        }
    } else {
        #pragma unroll
        for (int n8 = 0; n8 < 4; n8++) {
            const int clA = warp_n * 32 + n8 * 8 + qn;
            #pragma unroll
            for (int m_i = 0; m_i < 2; m_i++) {
                const int rlo = warp_m * 32 + m_i * 16 + qm;
                const int rhi = rlo + 8;
                const float* d = acc[m_i][n8];
                float e0 = exp2f(d[0] * INV_T_LOG2E);
                float e1 = exp2f(d[1] * INV_T_LOG2E);
                float e2 = exp2f(d[2] * INV_T_LOG2E);
                float e3 = exp2f(d[3] * INV_T_LOG2E);
                totLo[m_i] += ((rlo != clA)     ? e0 : 0.0f)
                            + ((rlo != clA + 1) ? e1 : 0.0f);
                totHi[m_i] += ((rhi != clA)     ? e2 : 0.0f)
                            + ((rhi != clA + 1) ? e3 : 0.0f);
                *(__nv_bfloat162*)(es + rlo * ESTRIDE + clA) = __floats2bfloat162_rn(e0, e1);
                *(__nv_bfloat162*)(es + rhi * ESTRIDE + clA) = __floats2bfloat162_rn(e2, e3);
            }
        }
    }

    // reduce row totals across the 4 col-lanes, stage to rt[row][warp_n]
    #pragma unroll
    for (int m_i = 0; m_i < 2; m_i++) {
        float vlo = totLo[m_i], vhi = totHi[m_i];
        vlo += __shfl_xor_sync(0xFFFFFFFFu, vlo, 1);
        vlo += __shfl_xor_sync(0xFFFFFFFFu, vlo, 2);
        vhi += __shfl_xor_sync(0xFFFFFFFFu, vhi, 1);
        vhi += __shfl_xor_sync(0xFFFFFFFFu, vhi, 2);
        if ((lane & 3) == 0) {
            int r = warp_m * 32 + m_i * 16 + qm;
            rt[r * 4 + warp_n]       = vlo;
            rt[(r + 8) * 4 + warp_n] = vhi;
        }
    }
    __syncthreads();

    // ---- epilogue phase 2: sparse extraction + nl = total - posSum
    if (tid < 128) {
        int r = tid;
        float tot = rt[r * 4] + rt[r * 4 + 1] + rt[r * 4 + 2] + rt[r * 4 + 3];
        float* gp = g_pos + (size_t)(row0 + r) * POS_STRIDE + bj * BLK_POS;
        float posSum = 0.0f;
        int k = 0;
        #pragma unroll
        for (int w = 0; w < 4; w++) {
            unsigned word = yb[r * 4 + w];
            while (word) {
                int b = __ffs(word) - 1;
                word &= word - 1;
                int cc = w * 32 + b;
                float e = __bfloat162float(es[r * ESTRIDE + cc]);
                gp[k++] = e;
                posSum += (offdiag || cc != r) ? e : 0.0f;
            }
        }
        g_bcnt[(size_t)(row0 + r) * 64 + bj] = k;
        g_nl_part[(size_t)(row0 + r) * NSLOT + bj] = tot - posSum;
    } else if (tid < 256 && offdiag) {
        int c = tid - 128;
        float tot = 0.0f;
        #pragma unroll
        for (int gg = 0; gg < 32; gg++) tot += cr[gg * ESTRIDE + c];
        float* gp = g_pos + (size_t)(col0 + c) * POS_STRIDE + bi * BLK_POS;
        float posSum = 0.0f;
        int k = 0;
        #pragma unroll
        for (int w = 0; w < 4; w++) {
            unsigned word = yb2[c * 4 + w];
            while (word) {
                int b = __ffs(word) - 1;
                word &= word - 1;
                float e = __bfloat162float(es[(w * 32 + b) * ESTRIDE + c]);
                gp[k++] = e;
                posSum += e;
            }
        }
        g_bcnt[(size_t)(col0 + c) * 64 + bi] = k;
        g_nl_part[(size_t)(col0 + c) * NSLOT + 64 + bi] = tot - posSum;
    }
}

// ---------------------------------------------------------------------------
// Per-row loss + fused final reduction. Row in block br has exactly 64 valid
// nl slots: row-role [br,64), col-role [64, 64+br). g_pos holds e values.
__global__ void k_rowloss(float* __restrict__ out) {
    __shared__ float bsum[8];
    int row  = blockIdx.x * 8 + (threadIdx.x >> 5);
    int lane = threadIdx.x & 31;
    int wrp  = threadIdx.x >> 5;
    int br = row >> 7;
    const float* p = g_nl_part + (size_t)row * NSLOT;
    float nl = 0.0f;
    #pragma unroll
    for (int bb = 0; bb < 2; bb++) {
        int i = lane + bb * 32;
        int s = (i < 64 - br) ? (br + i) : (64 + i - (64 - br));
        nl += p[s];
    }
    #pragma unroll
    for (int o = 16; o; o >>= 1) nl += __shfl_xor_sync(0xFFFFFFFFu, nl, o);

    const int* bc = g_bcnt + (size_t)row * 64;
    const float* ps = g_pos + (size_t)row * POS_STRIDE;
    float acc = 0.0f;
    int cnt = 0;
    #pragma unroll
    for (int bb = 0; bb < 2; bb++) {
        int b = lane + bb * 32;
        int c = bc[b];
        cnt += c;
        const float* pp = ps + b * BLK_POS;
        for (int k = 0; k < c; k++)
            acc += log1pf(__fdividef(nl, pp[k]));
    }
    #pragma unroll
    for (int o = 16; o; o >>= 1) {
        acc += __shfl_xor_sync(0xFFFFFFFFu, acc, o);
        cnt += __shfl_xor_sync(0xFFFFFFFFu, cnt, o);
    }
    if (lane == 0) bsum[wrp] = acc / (float)cnt;
    __syncthreads();
    if (threadIdx.x == 0) {
        float s = 0.0f;
        #pragma unroll
        for (int i = 0; i < 8; i++) s += bsum[i];
        atomicAdd(out, s * (1.0f / (float)NN));
    }
}

// ---------------------------------------------------------------------------
extern "C" void kernel_launch(void* const* d_in, const int* in_sizes, int n_in,
                              void* d_out, int out_size) {
    const float* x = (const float*)d_in[0];
    const float* y = (const float*)d_in[1];
    float* out = (float*)d_out;

    cudaFuncSetAttribute(k_tile, cudaFuncAttributeMaxDynamicSharedMemorySize, SM_TOT);

    k_normalize<<<NN / 8, 256>>>(x, out);                // idx 0 (zeroes out)
    k_pad<<<1, 32>>>();                                  // idx 1
    k_pad<<<1, 32>>>();                                  // idx 2
    k_tile<<<NBLK, 512, SM_TOT>>>(y);                    // idx 3 (ncu slot)
    k_rowloss<<<NN / 8, 256>>>(out);                     // idx 4
}

// round 16
// speedup vs baseline: 1.4404x; 1.0353x over previous
#include <cuda_runtime.h>
#include <cuda_bf16.h>
#include <math.h>
#include <cstdint>

// ContrastiveLoss N=8192 D=128 temp=0.05 — plain-bf16 HMMA, symmetric tiles,
// 512-thread CTAs, cp.async A/B tiles, fused y load, maskless epilogue
// (nl = total - posSum), bf16 e staging, 2-warp-per-row rowloss.
// loss = -mean_i [ (1/ppn_i) * sum_{j: y_ij=1} log( e_ij / (e_ij + nl_i) ) ]
// log(e/(e+nl)) = -log1p(nl/e), e = exp(cos/T).

#define NN 8192
#define DD 128
#define INV_T_LOG2E 28.853900817779268f   // 20 * log2(e)
#define NSLOT 128            // nl slots: row-role bj (0..63), col-role 64+bi
#define BLK_POS 32           // positive slots per (row, 128-col block)
#define POS_STRIDE 2048      // 64 blocks * 32

__device__ __nv_bfloat16 g_xhi[NN * DD];
__device__ float g_nl_part[(size_t)NN * NSLOT];
__device__ int   g_bcnt[(size_t)NN * 64];
__device__ float g_pos[(size_t)NN * POS_STRIDE];   // holds e values

// ---------------------------------------------------------------------------
__device__ __forceinline__ uint32_t smem_u32(const void* p) {
    uint32_t a;
    asm("{ .reg .u64 t; cvta.to.shared.u64 t, %1; cvt.u32.u64 %0, t; }" : "=r"(a) : "l"(p));
    return a;
}
__device__ __forceinline__ void cp_async16(uint32_t smem_addr, const void* gptr) {
    asm volatile("cp.async.ca.shared.global [%0], [%1], 16;"
        :: "r"(smem_addr), "l"(gptr) : "memory");
}
__device__ __forceinline__ void cp_async_commit_wait() {
    asm volatile("cp.async.commit_group;" ::: "memory");
    asm volatile("cp.async.wait_group 0;" ::: "memory");
}
__device__ __forceinline__ void ldmx4(uint32_t* r, uint32_t addr) {
    asm volatile("ldmatrix.sync.aligned.m8n8.x4.shared.b16 {%0,%1,%2,%3}, [%4];"
        : "=r"(r[0]), "=r"(r[1]), "=r"(r[2]), "=r"(r[3]) : "r"(addr));
}
__device__ __forceinline__ void mma_bf16(float* d, const uint32_t* a,
                                         uint32_t b0, uint32_t b1) {
    asm volatile("mma.sync.aligned.m16n8k16.row.col.f32.bf16.bf16.f32 "
        "{%0,%1,%2,%3}, {%4,%5,%6,%7}, {%8,%9}, {%0,%1,%2,%3};"
        : "+f"(d[0]), "+f"(d[1]), "+f"(d[2]), "+f"(d[3])
        : "r"(a[0]), "r"(a[1]), "r"(a[2]), "r"(a[3]), "r"(b0), "r"(b1));
}
__device__ __forceinline__ unsigned nib4(float4 v) {
    return (unsigned)(v.x != 0.0f) | ((unsigned)(v.y != 0.0f) << 1)
         | ((unsigned)(v.z != 0.0f) << 2) | ((unsigned)(v.w != 0.0f) << 3);
}

// ---------------------------------------------------------------------------
__global__ void k_normalize(const float* __restrict__ x, float* __restrict__ out) {
    if (blockIdx.x == 0 && threadIdx.x == 0) out[0] = 0.0f;
    int row  = blockIdx.x * 8 + (threadIdx.x >> 5);
    int lane = threadIdx.x & 31;
    float4 v = ((const float4*)(x + (size_t)row * DD))[lane];
    float ss = v.x * v.x + v.y * v.y + v.z * v.z + v.w * v.w;
    #pragma unroll
    for (int o = 16; o; o >>= 1) ss += __shfl_xor_sync(0xFFFFFFFFu, ss, o);
    float inv = rsqrtf(ss);
    float f[4] = {v.x * inv, v.y * inv, v.z * inv, v.w * inv};
    ushort4 hi4;
    unsigned short* hp = &hi4.x;
    #pragma unroll
    for (int i = 0; i < 4; i++) {
        __nv_bfloat16 h = __float2bfloat16(f[i]);
        hp[i] = *(unsigned short*)&h;
    }
    ((ushort4*)(g_xhi + (size_t)row * DD))[lane] = hi4;
}

// ---------------------------------------------------------------------------
// SMEM: A@0(32K)+B@32K(32K) until mainloop end; epilogue overlay in [0,64K):
//   es bf16 [128][132] @0 (33792B), cr float [32][132] @33792 (16896B),
//   rt float [128][4] @50688 (2048B). yb@65536 (2K), yb2@67584 (2K).
#define SM_A   0
#define SM_B   32768
#define SM_CR  33792
#define SM_RT  50688
#define SM_YB  65536
#define SM_YB2 67584
#define SM_TOT 69632
#define ESTRIDE 132
#define NBLK   2080          // 64*65/2

__global__ void __launch_bounds__(512, 2) k_tile(const float* __restrict__ y) {
    int bi = 0, rem = blockIdx.x;
    while (rem >= 64 - bi) { rem -= 64 - bi; bi++; }
    const int bj = bi + rem;
    const bool offdiag = (bi != bj);

    extern __shared__ char smem[];
    uint32_t sbase = smem_u32(smem);
    const int tid  = threadIdx.x;
    const int wid  = tid >> 5;       // 0..15
    const int lane = tid & 31;
    const int warp_m = wid >> 2;     // 0..3 (32 rows)
    const int warp_n = wid & 3;      // 0..3 (32 cols)
    const int row0 = bi * 128;
    const int col0 = bj * 128;

    unsigned* yb  = (unsigned*)(smem + SM_YB);
    unsigned* yb2 = (unsigned*)(smem + SM_YB2);
    __nv_bfloat16* es = (__nv_bfloat16*)smem;    // after mainloop
    float* cr = (float*)(smem + SM_CR);
    float* rt = (float*)(smem + SM_RT);

    // ---- A/B tile cp.async first (fire-and-forget; overlaps y phase)
    {
        const uint4* ah = (const uint4*)(g_xhi + (size_t)row0 * DD);
        const uint4* bh = (const uint4*)(g_xhi + (size_t)col0 * DD);
        #pragma unroll
        for (int i = 0; i < 4; i++) {
            int idx = tid + i * 512;
            int r   = idx >> 4;
            int c   = idx & 15;
            uint32_t so = (uint32_t)r * 256 + (uint32_t)((c ^ (r & 7)) * 16);
            cp_async16(sbase + SM_A + so, ah + idx);
            cp_async16(sbase + SM_B + so, bh + idx);
        }
    }

    // ---- y load (DRAM), high MLP: 8 threads/row, 4 float4 each
    {
        const int q8 = tid & 7;
        #pragma unroll
        for (int p = 0; p < 2; p++) {
            int r = p * 64 + (tid >> 3);
            const float4* yr = (const float4*)(y + (size_t)(row0 + r) * NN + col0) + q8 * 4;
            unsigned m = 0;
            #pragma unroll
            for (int k = 0; k < 4; k++) m |= nib4(yr[k]) << (k * 4);
            unsigned o = __shfl_xor_sync(0xFFFFFFFFu, m, 1);
            if (!(tid & 1)) yb[r * 4 + (q8 >> 1)] = m | (o << 16);
            if (offdiag) {
                const float4* yc = (const float4*)(y + (size_t)(col0 + r) * NN + row0) + q8 * 4;
                unsigned m2 = 0;
                #pragma unroll
                for (int k = 0; k < 4; k++) m2 |= nib4(yc[k]) << (k * 4);
                unsigned o2 = __shfl_xor_sync(0xFFFFFFFFu, m2, 1);
                if (!(tid & 1)) yb2[r * 4 + (q8 >> 1)] = m2 | (o2 << 16);
            }
        }
    }
    cp_async_commit_wait();
    __syncthreads();

    // ---- mainloop: 32x32 warp tile, 64 MMAs/warp
    float acc[2][4][4];
    #pragma unroll
    for (int i = 0; i < 2; i++)
        #pragma unroll
        for (int j = 0; j < 4; j++)
            #pragma unroll
            for (int q = 0; q < 4; q++) acc[i][j][q] = 0.0f;

    const uint32_t lane_row = lane & 15;
    const uint32_t kb  = lane >> 4;
    const uint32_t key = lane & 7;
    const uint32_t a_base = sbase + SM_A + (warp_m * 32 + lane_row) * 256;
    const uint32_t b_base = sbase + SM_B + (warp_n * 32 + lane_row) * 256;

    #pragma unroll
    for (int k16 = 0; k16 < 8; k16++) {
        uint32_t ca = (((uint32_t)k16 * 2 + kb) ^ key) * 16;
        uint32_t a0[4], a1[4], b0[4], b1[4];
        ldmx4(a0, a_base + ca);
        ldmx4(a1, a_base + 4096 + ca);
        ldmx4(b0, b_base + ca);
        ldmx4(b1, b_base + 4096 + ca);
        mma_bf16(acc[0][0], a0, b0[0], b0[2]);
        mma_bf16(acc[0][1], a0, b0[1], b0[3]);
        mma_bf16(acc[0][2], a0, b1[0], b1[2]);
        mma_bf16(acc[0][3], a0, b1[1], b1[3]);
        mma_bf16(acc[1][0], a1, b0[0], b0[2]);
        mma_bf16(acc[1][1], a1, b0[1], b0[3]);
        mma_bf16(acc[1][2], a1, b1[0], b1[2]);
        mma_bf16(acc[1][3], a1, b1[1], b1[3]);
    }
    __syncthreads();   // A/B smem dead; es/cr/rt overlay takes over

    // ---- epilogue phase 1: maskless totals + bf16 e staging
    const int qm = lane >> 2;
    const int qn = (lane & 3) * 2;
    const int g  = warp_m * 8 + qm;
    float totLo[2] = {0.f, 0.f};
    float totHi[2] = {0.f, 0.f};

    if (offdiag) {
        #pragma unroll
        for (int n8 = 0; n8 < 4; n8++) {
            const int clA = warp_n * 32 + n8 * 8 + qn;
            float negc0 = 0.0f, negc1 = 0.0f;
            #pragma unroll
            for (int m_i = 0; m_i < 2; m_i++) {
                const int rlo = warp_m * 32 + m_i * 16 + qm;
                const int rhi = rlo + 8;
                const float* d = acc[m_i][n8];
                float e0 = exp2f(d[0] * INV_T_LOG2E);
                float e1 = exp2f(d[1] * INV_T_LOG2E);
                float e2 = exp2f(d[2] * INV_T_LOG2E);
                float e3 = exp2f(d[3] * INV_T_LOG2E);
                totLo[m_i] += e0 + e1;
                totHi[m_i] += e2 + e3;
                negc0 += e0 + e2;
                negc1 += e1 + e3;
                *(__nv_bfloat162*)(es + rlo * ESTRIDE + clA) = __floats2bfloat162_rn(e0, e1);
                *(__nv_bfloat162*)(es + rhi * ESTRIDE + clA) = __floats2bfloat162_rn(e2, e3);
            }
            cr[g * ESTRIDE + clA]     = negc0;
            cr[g * ESTRIDE + clA + 1] = negc1;
        }
    } else {
        #pragma unroll
        for (int n8 = 0; n8 < 4; n8++) {
            const int clA = warp_n * 32 + n8 * 8 + qn;
            #pragma unroll
            for (int m_i = 0; m_i < 2; m_i++) {
                const int rlo = warp_m * 32 + m_i * 16 + qm;
                const int rhi = rlo + 8;
                const float* d = acc[m_i][n8];
                float e0 = exp2f(d[0] * INV_T_LOG2E);
                float e1 = exp2f(d[1] * INV_T_LOG2E);
                float e2 = exp2f(d[2] * INV_T_LOG2E);
                float e3 = exp2f(d[3] * INV_T_LOG2E);
                totLo[m_i] += ((rlo != clA)     ? e0 : 0.0f)
                            + ((rlo != clA + 1) ? e1 : 0.0f);
                totHi[m_i] += ((rhi != clA)     ? e2 : 0.0f)
                            + ((rhi != clA + 1) ? e3 : 0.0f);
                *(__nv_bfloat162*)(es + rlo * ESTRIDE + clA) = __floats2bfloat162_rn(e0, e1);
                *(__nv_bfloat162*)(es + rhi * ESTRIDE + clA) = __floats2bfloat162_rn(e2, e3);
            }
        }
    }

    // reduce row totals across the 4 col-lanes, stage to rt[row][warp_n]
    #pragma unroll
    for (int m_i = 0; m_i < 2; m_i++) {
        float vlo = totLo[m_i], vhi = totHi[m_i];
        vlo += __shfl_xor_sync(0xFFFFFFFFu, vlo, 1);
        vlo += __shfl_xor_sync(0xFFFFFFFFu, vlo, 2);
        vhi += __shfl_xor_sync(0xFFFFFFFFu, vhi, 1);
        vhi += __shfl_xor_sync(0xFFFFFFFFu, vhi, 2);
        if ((lane & 3) == 0) {
            int r = warp_m * 32 + m_i * 16 + qm;
            rt[r * 4 + warp_n]       = vlo;
            rt[(r + 8) * 4 + warp_n] = vhi;
        }
    }
    __syncthreads();

    // ---- epilogue phase 2: sparse extraction + nl = total - posSum
    if (tid < 128) {
        int r = tid;
        float tot = rt[r * 4] + rt[r * 4 + 1] + rt[r * 4 + 2] + rt[r * 4 + 3];
        float* gp = g_pos + (size_t)(row0 + r) * POS_STRIDE + bj * BLK_POS;
        float posSum = 0.0f;
        int k = 0;
        #pragma unroll
        for (int w = 0; w < 4; w++) {
            unsigned word = yb[r * 4 + w];
            while (word) {
                int b = __ffs(word) - 1;
                word &= word - 1;
                int cc = w * 32 + b;
                float e = __bfloat162float(es[r * ESTRIDE + cc]);
                gp[k++] = e;
                posSum += (offdiag || cc != r) ? e : 0.0f;
            }
        }
        g_bcnt[(size_t)(row0 + r) * 64 + bj] = k;
        g_nl_part[(size_t)(row0 + r) * NSLOT + bj] = tot - posSum;
    } else if (tid < 256 && offdiag) {
        int c = tid - 128;
        float tot = 0.0f;
        #pragma unroll
        for (int gg = 0; gg < 32; gg++) tot += cr[gg * ESTRIDE + c];
        float* gp = g_pos + (size_t)(col0 + c) * POS_STRIDE + bi * BLK_POS;
        float posSum = 0.0f;
        int k = 0;
        #pragma unroll
        for (int w = 0; w < 4; w++) {
            unsigned word = yb2[c * 4 + w];
            while (word) {
                int b = __ffs(word) - 1;
                word &= word - 1;
                float e = __bfloat162float(es[(w * 32 + b) * ESTRIDE + c]);
                gp[k++] = e;
                posSum += e;
            }
        }
        g_bcnt[(size_t)(col0 + c) * 64 + bi] = k;
        g_nl_part[(size_t)(col0 + c) * NSLOT + 64 + bi] = tot - posSum;
    }
}

// ---------------------------------------------------------------------------
// Per-row loss + fused final reduction. 2 warps per row (512 thr, 8 rows/blk).
// nl slots for row in block br: row-role [br,64) then col-role [64,64+br).
__global__ void __launch_bounds__(512) k_rowloss(float* __restrict__ out) {
    __shared__ float nlp[16];
    __shared__ float asum[16];
    __shared__ int   csum[16];
    __shared__ float bsum[8];
    int tid  = threadIdx.x;
    int wrp  = tid >> 5;         // 0..15
    int lane = tid & 31;
    int rloc = wrp >> 1;         // 0..7
    int half = wrp & 1;          // 0/1
    int row  = blockIdx.x * 8 + rloc;
    int br   = row >> 7;

    // nl partial: this warp covers slot indices i in [half*32, half*32+32)
    {
        int i = half * 32 + lane;
        int s = (i < 64 - br) ? (br + i) : (64 + i - (64 - br));
        float nl = g_nl_part[(size_t)row * NSLOT + s];
        #pragma unroll
        for (int o = 16; o; o >>= 1) nl += __shfl_xor_sync(0xFFFFFFFFu, nl, o);
        if (lane == 0) nlp[wrp] = nl;
    }
    __syncthreads();
    float nl = nlp[rloc * 2] + nlp[rloc * 2 + 1];

    // positives: this warp covers blocks [half*32, half*32+32), one per lane
    const int* bc = g_bcnt + (size_t)row * 64;
    const float* ps = g_pos + (size_t)row * POS_STRIDE;
    int b = half * 32 + lane;
    int c = bc[b];
    float acc = 0.0f;
    const float* pp = ps + b * BLK_POS;
    for (int k = 0; k < c; k++)
        acc += log1pf(__fdividef(nl, pp[k]));
    int cnt = c;
    #pragma unroll
    for (int o = 16; o; o >>= 1) {
        acc += __shfl_xor_sync(0xFFFFFFFFu, acc, o);
        cnt += __shfl_xor_sync(0xFFFFFFFFu, cnt, o);
    }
    if (lane == 0) { asum[wrp] = acc; csum[wrp] = cnt; }
    __syncthreads();
    if (half == 0 && lane == 0) {
        float a = asum[wrp] + asum[wrp + 1];
        int   n = csum[wrp] + csum[wrp + 1];
        bsum[rloc] = a / (float)n;
    }
    __syncthreads();
    if (tid == 0) {
        float s = 0.0f;
        #pragma unroll
        for (int i = 0; i < 8; i++) s += bsum[i];
        atomicAdd(out, s * (1.0f / (float)NN));
    }
}

// ---------------------------------------------------------------------------
extern "C" void kernel_launch(void* const* d_in, const int* in_sizes, int n_in,
                              void* d_out, int out_size) {
    const float* x = (const float*)d_in[0];
    const float* y = (const float*)d_in[1];
    float* out = (float*)d_out;

    cudaFuncSetAttribute(k_tile, cudaFuncAttributeMaxDynamicSharedMemorySize, SM_TOT);

    k_normalize<<<NN / 8, 256>>>(x, out);                // zeroes out
    k_tile<<<NBLK, 512, SM_TOT>>>(y);
    k_rowloss<<<NN / 8, 512>>>(out);
}

// round 17
// speedup vs baseline: 1.5332x; 1.0644x over previous
#include <cuda_runtime.h>
#include <cuda_bf16.h>
#include <math.h>
#include <cstdint>

// ContrastiveLoss N=8192 D=128 temp=0.05 — plain-bf16 HMMA, symmetric tiles,
// 512-thread CTAs, cp.async A/B tiles, streaming y load, maskless epilogue
// (nl = total - posSum), bf16 e staging, pair-parallel phase 2.
// loss = -mean_i [ (1/ppn_i) * sum_{j: y_ij=1} log( e_ij / (e_ij + nl_i) ) ]
// log(e/(e+nl)) = -log1p(nl/e), e = exp(cos/T).

#define NN 8192
#define DD 128
#define INV_T_LOG2E 28.853900817779268f   // 20 * log2(e)
#define NSLOT 128            // nl slots: row-role bj (0..63), col-role 64+bi
#define BLK_POS 32           // positive slots per (row, 128-col block)
#define POS_STRIDE 2048      // 64 blocks * 32

__device__ __nv_bfloat16 g_xhi[NN * DD];
__device__ float g_nl_part[(size_t)NN * NSLOT];
__device__ int   g_bcnt[(size_t)NN * 64];
__device__ float g_pos[(size_t)NN * POS_STRIDE];   // holds e values

// ---------------------------------------------------------------------------
__device__ __forceinline__ uint32_t smem_u32(const void* p) {
    uint32_t a;
    asm("{ .reg .u64 t; cvta.to.shared.u64 t, %1; cvt.u32.u64 %0, t; }" : "=r"(a) : "l"(p));
    return a;
}
__device__ __forceinline__ void cp_async16(uint32_t smem_addr, const void* gptr) {
    asm volatile("cp.async.ca.shared.global [%0], [%1], 16;"
        :: "r"(smem_addr), "l"(gptr) : "memory");
}
__device__ __forceinline__ void cp_async_commit_wait() {
    asm volatile("cp.async.commit_group;" ::: "memory");
    asm volatile("cp.async.wait_group 0;" ::: "memory");
}
__device__ __forceinline__ void ldmx4(uint32_t* r, uint32_t addr) {
    asm volatile("ldmatrix.sync.aligned.m8n8.x4.shared.b16 {%0,%1,%2,%3}, [%4];"
        : "=r"(r[0]), "=r"(r[1]), "=r"(r[2]), "=r"(r[3]) : "r"(addr));
}
__device__ __forceinline__ void mma_bf16(float* d, const uint32_t* a,
                                         uint32_t b0, uint32_t b1) {
    asm volatile("mma.sync.aligned.m16n8k16.row.col.f32.bf16.bf16.f32 "
        "{%0,%1,%2,%3}, {%4,%5,%6,%7}, {%8,%9}, {%0,%1,%2,%3};"
        : "+f"(d[0]), "+f"(d[1]), "+f"(d[2]), "+f"(d[3])
        : "r"(a[0]), "r"(a[1]), "r"(a[2]), "r"(a[3]), "r"(b0), "r"(b1));
}
__device__ __forceinline__ unsigned nib4(float4 v) {
    return (unsigned)(v.x != 0.0f) | ((unsigned)(v.y != 0.0f) << 1)
         | ((unsigned)(v.z != 0.0f) << 2) | ((unsigned)(v.w != 0.0f) << 3);
}

// ---------------------------------------------------------------------------
__global__ void k_normalize(const float* __restrict__ x, float* __restrict__ out) {
    if (blockIdx.x == 0 && threadIdx.x == 0) out[0] = 0.0f;
    int row  = blockIdx.x * 8 + (threadIdx.x >> 5);
    int lane = threadIdx.x & 31;
    float4 v = ((const float4*)(x + (size_t)row * DD))[lane];
    float ss = v.x * v.x + v.y * v.y + v.z * v.z + v.w * v.w;
    #pragma unroll
    for (int o = 16; o; o >>= 1) ss += __shfl_xor_sync(0xFFFFFFFFu, ss, o);
    float inv = rsqrtf(ss);
    float f[4] = {v.x * inv, v.y * inv, v.z * inv, v.w * inv};
    ushort4 hi4;
    unsigned short* hp = &hi4.x;
    #pragma unroll
    for (int i = 0; i < 4; i++) {
        __nv_bfloat16 h = __float2bfloat16(f[i]);
        hp[i] = *(unsigned short*)&h;
    }
    ((ushort4*)(g_xhi + (size_t)row * DD))[lane] = hi4;
}

// ---------------------------------------------------------------------------
// SMEM: A@0(32K)+B@32K(32K) until mainloop end; epilogue overlay in [0,64K):
//   es bf16 [128][132] @0 (33792B), cr float [32][132] @33792 (16896B),
//   rt float [128][4] @50688 (2048B). yb@65536 (2K), yb2@67584 (2K).
#define SM_A   0
#define SM_B   32768
#define SM_CR  33792
#define SM_RT  50688
#define SM_YB  65536
#define SM_YB2 67584
#define SM_TOT 69632
#define ESTRIDE 132
#define NBLK   2080          // 64*65/2

__global__ void __launch_bounds__(512, 2) k_tile(const float* __restrict__ y) {
    int bi = 0, rem = blockIdx.x;
    while (rem >= 64 - bi) { rem -= 64 - bi; bi++; }
    const int bj = bi + rem;
    const bool offdiag = (bi != bj);

    extern __shared__ char smem[];
    uint32_t sbase = smem_u32(smem);
    const int tid  = threadIdx.x;
    const int wid  = tid >> 5;       // 0..15
    const int lane = tid & 31;
    const int warp_m = wid >> 2;     // 0..3 (32 rows)
    const int warp_n = wid & 3;      // 0..3 (32 cols)
    const int row0 = bi * 128;
    const int col0 = bj * 128;

    unsigned* yb  = (unsigned*)(smem + SM_YB);
    unsigned* yb2 = (unsigned*)(smem + SM_YB2);
    __nv_bfloat16* es = (__nv_bfloat16*)smem;    // after mainloop
    float* cr = (float*)(smem + SM_CR);
    float* rt = (float*)(smem + SM_RT);

    // ---- A/B tile cp.async first (fire-and-forget; overlaps y phase)
    {
        const uint4* ah = (const uint4*)(g_xhi + (size_t)row0 * DD);
        const uint4* bh = (const uint4*)(g_xhi + (size_t)col0 * DD);
        #pragma unroll
        for (int i = 0; i < 4; i++) {
            int idx = tid + i * 512;
            int r   = idx >> 4;
            int c   = idx & 15;
            uint32_t so = (uint32_t)r * 256 + (uint32_t)((c ^ (r & 7)) * 16);
            cp_async16(sbase + SM_A + so, ah + idx);
            cp_async16(sbase + SM_B + so, bh + idx);
        }
    }

    // ---- y load (DRAM, streaming), high MLP: 8 threads/row, 4 float4 each
    {
        const int q8 = tid & 7;
        #pragma unroll
        for (int p = 0; p < 2; p++) {
            int r = p * 64 + (tid >> 3);
            const float4* yr = (const float4*)(y + (size_t)(row0 + r) * NN + col0) + q8 * 4;
            unsigned m = 0;
            #pragma unroll
            for (int k = 0; k < 4; k++) m |= nib4(__ldcs(yr + k)) << (k * 4);
            unsigned o = __shfl_xor_sync(0xFFFFFFFFu, m, 1);
            if (!(tid & 1)) yb[r * 4 + (q8 >> 1)] = m | (o << 16);
            if (offdiag) {
                const float4* yc = (const float4*)(y + (size_t)(col0 + r) * NN + row0) + q8 * 4;
                unsigned m2 = 0;
                #pragma unroll
                for (int k = 0; k < 4; k++) m2 |= nib4(__ldcs(yc + k)) << (k * 4);
                unsigned o2 = __shfl_xor_sync(0xFFFFFFFFu, m2, 1);
                if (!(tid & 1)) yb2[r * 4 + (q8 >> 1)] = m2 | (o2 << 16);
            }
        }
    }
    cp_async_commit_wait();
    __syncthreads();

    // ---- mainloop: 32x32 warp tile, 64 MMAs/warp
    float acc[2][4][4];
    #pragma unroll
    for (int i = 0; i < 2; i++)
        #pragma unroll
        for (int j = 0; j < 4; j++)
            #pragma unroll
            for (int q = 0; q < 4; q++) acc[i][j][q] = 0.0f;

    const uint32_t lane_row = lane & 15;
    const uint32_t kb  = lane >> 4;
    const uint32_t key = lane & 7;
    const uint32_t a_base = sbase + SM_A + (warp_m * 32 + lane_row) * 256;
    const uint32_t b_base = sbase + SM_B + (warp_n * 32 + lane_row) * 256;

    #pragma unroll
    for (int k16 = 0; k16 < 8; k16++) {
        uint32_t ca = (((uint32_t)k16 * 2 + kb) ^ key) * 16;
        uint32_t a0[4], a1[4], b0[4], b1[4];
        ldmx4(a0, a_base + ca);
        ldmx4(a1, a_base + 4096 + ca);
        ldmx4(b0, b_base + ca);
        ldmx4(b1, b_base + 4096 + ca);
        mma_bf16(acc[0][0], a0, b0[0], b0[2]);
        mma_bf16(acc[0][1], a0, b0[1], b0[3]);
        mma_bf16(acc[0][2], a0, b1[0], b1[2]);
        mma_bf16(acc[0][3], a0, b1[1], b1[3]);
        mma_bf16(acc[1][0], a1, b0[0], b0[2]);
        mma_bf16(acc[1][1], a1, b0[1], b0[3]);
        mma_bf16(acc[1][2], a1, b1[0], b1[2]);
        mma_bf16(acc[1][3], a1, b1[1], b1[3]);
    }
    __syncthreads();   // A/B smem dead; es/cr/rt overlay takes over

    // ---- epilogue phase 1: maskless totals + bf16 e staging
    const int qm = lane >> 2;
    const int qn = (lane & 3) * 2;
    const int g  = warp_m * 8 + qm;
    float totLo[2] = {0.f, 0.f};
    float totHi[2] = {0.f, 0.f};

    if (offdiag) {
        #pragma unroll
        for (int n8 = 0; n8 < 4; n8++) {
            const int clA = warp_n * 32 + n8 * 8 + qn;
            float negc0 = 0.0f, negc1 = 0.0f;
            #pragma unroll
            for (int m_i = 0; m_i < 2; m_i++) {
                const int rlo = warp_m * 32 + m_i * 16 + qm;
                const int rhi = rlo + 8;
                const float* d = acc[m_i][n8];
                float e0 = exp2f(d[0] * INV_T_LOG2E);
                float e1 = exp2f(d[1] * INV_T_LOG2E);
                float e2 = exp2f(d[2] * INV_T_LOG2E);
                float e3 = exp2f(d[3] * INV_T_LOG2E);
                totLo[m_i] += e0 + e1;
                totHi[m_i] += e2 + e3;
                negc0 += e0 + e2;
                negc1 += e1 + e3;
                *(__nv_bfloat162*)(es + rlo * ESTRIDE + clA) = __floats2bfloat162_rn(e0, e1);
                *(__nv_bfloat162*)(es + rhi * ESTRIDE + clA) = __floats2bfloat162_rn(e2, e3);
            }
            cr[g * ESTRIDE + clA]     = negc0;
            cr[g * ESTRIDE + clA + 1] = negc1;
        }
    } else {
        #pragma unroll
        for (int n8 = 0; n8 < 4; n8++) {
            const int clA = warp_n * 32 + n8 * 8 + qn;
            #pragma unroll
            for (int m_i = 0; m_i < 2; m_i++) {
                const int rlo = warp_m * 32 + m_i * 16 + qm;
                const int rhi = rlo + 8;
                const float* d = acc[m_i][n8];
                float e0 = exp2f(d[0] * INV_T_LOG2E);
                float e1 = exp2f(d[1] * INV_T_LOG2E);
                float e2 = exp2f(d[2] * INV_T_LOG2E);
                float e3 = exp2f(d[3] * INV_T_LOG2E);
                totLo[m_i] += ((rlo != clA)     ? e0 : 0.0f)
                            + ((rlo != clA + 1) ? e1 : 0.0f);
                totHi[m_i] += ((rhi != clA)     ? e2 : 0.0f)
                            + ((rhi != clA + 1) ? e3 : 0.0f);
                *(__nv_bfloat162*)(es + rlo * ESTRIDE + clA) = __floats2bfloat162_rn(e0, e1);
                *(__nv_bfloat162*)(es + rhi * ESTRIDE + clA) = __floats2bfloat162_rn(e2, e3);
            }
        }
    }

    // reduce row totals across the 4 col-lanes, stage to rt[row][warp_n]
    #pragma unroll
    for (int m_i = 0; m_i < 2; m_i++) {
        float vlo = totLo[m_i], vhi = totHi[m_i];
        vlo += __shfl_xor_sync(0xFFFFFFFFu, vlo, 1);
        vlo += __shfl_xor_sync(0xFFFFFFFFu, vlo, 2);
        vhi += __shfl_xor_sync(0xFFFFFFFFu, vhi, 1);
        vhi += __shfl_xor_sync(0xFFFFFFFFu, vhi, 2);
        if ((lane & 3) == 0) {
            int r = warp_m * 32 + m_i * 16 + qm;
            rt[r * 4 + warp_n]       = vlo;
            rt[(r + 8) * 4 + warp_n] = vhi;
        }
    }
    __syncthreads();

    // ---- epilogue phase 2 (pair-parallel): threads (2r,2r+1) per row,
    // (256+2c, 256+2c+1) per col. h=0 handles words 0-1, h=1 words 2-3.
    if (tid < 256) {
        int r = tid >> 1, h = tid & 1;
        float tot = rt[r * 4 + h * 2] + rt[r * 4 + h * 2 + 1];
        tot += __shfl_xor_sync(0xFFFFFFFFu, tot, 1);
        unsigned wA = yb[r * 4 + h * 2];
        unsigned wB = yb[r * 4 + h * 2 + 1];
        int myc = __popc(wA) + __popc(wB);
        int otherc = __shfl_xor_sync(0xFFFFFFFFu, myc, 1);
        int kk = h ? otherc : 0;
        float* gp = g_pos + (size_t)(row0 + r) * POS_STRIDE + bj * BLK_POS;
        float posSum = 0.0f;
        #pragma unroll
        for (int w = 0; w < 2; w++) {
            unsigned word = w ? wB : wA;
            int cbase = (h * 2 + w) * 32;
            while (word) {
                int b = __ffs(word) - 1;
                word &= word - 1;
                int cc = cbase + b;
                float e = __bfloat162float(es[r * ESTRIDE + cc]);
                gp[kk++] = e;
                posSum += (offdiag || cc != r) ? e : 0.0f;
            }
        }
        float posTot = posSum + __shfl_xor_sync(0xFFFFFFFFu, posSum, 1);
        if (h == 0) {
            g_bcnt[(size_t)(row0 + r) * 64 + bj] = myc + otherc;
            g_nl_part[(size_t)(row0 + r) * NSLOT + bj] = tot - posTot;
        }
    } else if (offdiag) {
        int c = (tid - 256) >> 1, h = tid & 1;
        float tot = 0.0f;
        #pragma unroll
        for (int gg = 0; gg < 16; gg++) tot += cr[(h * 16 + gg) * ESTRIDE + c];
        tot += __shfl_xor_sync(0xFFFFFFFFu, tot, 1);
        unsigned wA = yb2[c * 4 + h * 2];
        unsigned wB = yb2[c * 4 + h * 2 + 1];
        int myc = __popc(wA) + __popc(wB);
        int otherc = __shfl_xor_sync(0xFFFFFFFFu, myc, 1);
        int kk = h ? otherc : 0;
        float* gp = g_pos + (size_t)(col0 + c) * POS_STRIDE + bi * BLK_POS;
        float posSum = 0.0f;
        #pragma unroll
        for (int w = 0; w < 2; w++) {
            unsigned word = w ? wB : wA;
            int rbase = (h * 2 + w) * 32;
            while (word) {
                int b = __ffs(word) - 1;
                word &= word - 1;
                float e = __bfloat162float(es[(rbase + b) * ESTRIDE + c]);
                gp[kk++] = e;
                posSum += e;
            }
        }
        float posTot = posSum + __shfl_xor_sync(0xFFFFFFFFu, posSum, 1);
        if (h == 0) {
            g_bcnt[(size_t)(col0 + c) * 64 + bi] = myc + otherc;
            g_nl_part[(size_t)(col0 + c) * NSLOT + 64 + bi] = tot - posTot;
        }
    }
}

// ---------------------------------------------------------------------------
// Per-row loss + fused final reduction. 2 warps per row (512 thr, 8 rows/blk).
// nl slots for row in block br: row-role [br,64) then col-role [64,64+br).
__global__ void __launch_bounds__(512) k_rowloss(float* __restrict__ out) {
    __shared__ float nlp[16];
    __shared__ float asum[16];
    __shared__ int   csum[16];
    __shared__ float bsum[8];
    int tid  = threadIdx.x;
    int wrp  = tid >> 5;
    int lane = tid & 31;
    int rloc = wrp >> 1;
    int half = wrp & 1;
    int row  = blockIdx.x * 8 + rloc;
    int br   = row >> 7;

    {
        int i = half * 32 + lane;
        int s = (i < 64 - br) ? (br + i) : (64 + i - (64 - br));
        float nl = g_nl_part[(size_t)row * NSLOT + s];
        #pragma unroll
        for (int o = 16; o; o >>= 1) nl += __shfl_xor_sync(0xFFFFFFFFu, nl, o);
        if (lane == 0) nlp[wrp] = nl;
    }
    __syncthreads();
    float nl = nlp[rloc * 2] + nlp[rloc * 2 + 1];

    const int* bc = g_bcnt + (size_t)row * 64;
    const float* ps = g_pos + (size_t)row * POS_STRIDE;
    int b = half * 32 + lane;
    int c = bc[b];
    float acc = 0.0f;
    const float* pp = ps + b * BLK_POS;
    for (int k = 0; k < c; k++)
        acc += log1pf(__fdividef(nl, pp[k]));
    int cnt = c;
    #pragma unroll
    for (int o = 16; o; o >>= 1) {
        acc += __shfl_xor_sync(0xFFFFFFFFu, acc, o);
        cnt += __shfl_xor_sync(0xFFFFFFFFu, cnt, o);
    }
    if (lane == 0) { asum[wrp] = acc; csum[wrp] = cnt; }
    __syncthreads();
    if (half == 0 && lane == 0) {
        float a = asum[wrp] + asum[wrp + 1];
        int   n = csum[wrp] + csum[wrp + 1];
        bsum[rloc] = a / (float)n;
    }
    __syncthreads();
    if (tid == 0) {
        float s = 0.0f;
        #pragma unroll
        for (int i = 0; i < 8; i++) s += bsum[i];
        atomicAdd(out, s * (1.0f / (float)NN));
    }
}

// ---------------------------------------------------------------------------
extern "C" void kernel_launch(void* const* d_in, const int* in_sizes, int n_in,
                              void* d_out, int out_size) {
    const float* x = (const float*)d_in[0];
    const float* y = (const float*)d_in[1];
    float* out = (float*)d_out;

    cudaFuncSetAttribute(k_tile, cudaFuncAttributeMaxDynamicSharedMemorySize, SM_TOT);

    k_normalize<<<NN / 8, 256>>>(x, out);                // zeroes out
    k_tile<<<NBLK, 512, SM_TOT>>>(y);
    k_rowloss<<<NN / 8, 512>>>(out);
}